// round 13
// baseline (speedup 1.0000x reference)
#include <cuda_runtime.h>
#include <cuda_bf16.h>
#include <cstdint>
#include <climits>

#define BATCH   8192
#define DINA    4096
#define DINB    2048
#define DLAT    256
#define NCODE   8192
#define BETA_F  0.25f

// ---------------- scratch (static __device__ — no allocation) ----------------
__device__ float g_ze_a0[BATCH * DLAT];
__device__ float g_ze_a1[BATCH * DLAT];
__device__ float g_ze_b0[BATCH * DLAT];
__device__ float g_ze_b1[BATCH * DLAT];
__device__ float g_h1a[2 * BATCH * DLAT];
__device__ float g_h1b[2 * BATCH * DLAT];
__device__ double g_zz_a[BATCH];
__device__ double g_zz_b[BATCH];
__device__ int g_qmax_a[BATCH];
__device__ int g_qmax_b[BATCH];
__device__ int g_win_a[BATCH];
__device__ int g_win_b[BATCH];
__device__ short g_q_a[(size_t)BATCH * NCODE];
__device__ short g_q_b[(size_t)BATCH * NCODE];
// bf16 splits
__device__ __nv_bfloat16 g_zh_a[BATCH * DLAT];
__device__ __nv_bfloat16 g_zl_a[BATCH * DLAT];
__device__ __nv_bfloat16 g_zh_b[BATCH * DLAT];
__device__ __nv_bfloat16 g_zl_b[BATCH * DLAT];
__device__ __nv_bfloat16 g_eh[NCODE * DLAT];
__device__ __nv_bfloat16 g_el[NCODE * DLAT];
__device__ __nv_bfloat16 g_zqh[2 * BATCH * DLAT];
__device__ __nv_bfloat16 g_zql[2 * BATCH * DLAT];
__device__ __nv_bfloat16 g_s1h_a[2 * BATCH * DLAT];
__device__ __nv_bfloat16 g_s1l_a[2 * BATCH * DLAT];
__device__ __nv_bfloat16 g_s0h_a[2 * BATCH * DLAT];
__device__ __nv_bfloat16 g_s0l_a[2 * BATCH * DLAT];
__device__ __nv_bfloat16 g_s1h_b[2 * BATCH * DLAT];
__device__ __nv_bfloat16 g_s1l_b[2 * BATCH * DLAT];
__device__ __nv_bfloat16 g_s0h_b[2 * BATCH * DLAT];
__device__ __nv_bfloat16 g_s0l_b[2 * BATCH * DLAT];
__device__ __nv_bfloat16 g_wth_a[DINA * DLAT];
__device__ __nv_bfloat16 g_wtl_a[DINA * DLAT];
__device__ __nv_bfloat16 g_wth_b[DINB * DLAT];
__device__ __nv_bfloat16 g_wtl_b[DINB * DLAT];
__device__ __nv_bfloat16 g_rwth_a[2 * DLAT * DLAT];
__device__ __nv_bfloat16 g_rwtl_a[2 * DLAT * DLAT];
__device__ __nv_bfloat16 g_rwth_b[2 * DLAT * DLAT];
__device__ __nv_bfloat16 g_rwtl_b[2 * DLAT * DLAT];

__device__ __forceinline__ uint32_t smem_u32(const void* p) {
    uint32_t a;
    asm("{ .reg .u64 t; cvta.to.shared.u64 t, %1; cvt.u32.u64 %0, t; }"
        : "=r"(a) : "l"(p));
    return a;
}
__device__ __forceinline__ void cp16(uint32_t s, const void* g) {
    asm volatile("cp.async.cg.shared.global [%0], [%1], 16;" :: "r"(s), "l"(g));
}
// packed f32x2 helpers — each lane is an independent IEEE-rn fp32 FMA
__device__ __forceinline__ uint64_t pack2f(float x, float y) {
    uint64_t r; asm("mov.b64 %0, {%1, %2};" : "=l"(r) : "f"(x), "f"(y)); return r;
}
__device__ __forceinline__ uint64_t splat2f(float x) {
    uint64_t r; asm("mov.b64 %0, {%1, %1};" : "=l"(r) : "f"(x)); return r;
}
__device__ __forceinline__ void unpack2f(uint64_t v, float& x, float& y) {
    asm("mov.b64 {%0, %1}, %2;" : "=f"(x), "=f"(y) : "l"(v));
}
__device__ __forceinline__ void ffma2(uint64_t& d, uint64_t a, uint64_t b) {
    asm("fma.rn.f32x2 %0, %1, %2, %0;" : "+l"(d) : "l"(a), "l"(b));
}

// ---------------- small helpers ----------------
__global__ void init_qmax_kernel() {
    int i = blockIdx.x * blockDim.x + threadIdx.x;
    if (i < BATCH) { g_qmax_a[i] = INT_MIN; g_qmax_b[i] = INT_MIN; }
}

__global__ void zz_kernel(const float* __restrict__ Z0, const float* __restrict__ Z1,
                          double* __restrict__ zz0, double* __restrict__ zz1) {
    const float* Z = blockIdx.y ? Z1 : Z0;
    double* zz = blockIdx.y ? zz1 : zz0;
    int row  = blockIdx.x * 8 + (threadIdx.x >> 5);
    int lane = threadIdx.x & 31;
    const float4* zp = reinterpret_cast<const float4*>(Z) + (size_t)row * (DLAT / 4);
    double s = 0.0;
#pragma unroll
    for (int t = 0; t < 2; t++) {
        float4 v = zp[lane + 32 * t];
        s += (double)v.x * v.x + (double)v.y * v.y
           + (double)v.z * v.z + (double)v.w * v.w;
    }
#pragma unroll
    for (int o = 16; o; o >>= 1) s += __shfl_down_sync(0xffffffffu, s, o);
    if (lane == 0) zz[row] = s;
}

__global__ void split1_kernel(const float* __restrict__ x,
                              __nv_bfloat16* __restrict__ hi,
                              __nv_bfloat16* __restrict__ lo, int n4)
{
    int i = blockIdx.x * blockDim.x + threadIdx.x;
    if (i >= n4) return;
    float4 v = ((const float4*)x)[i];
    __nv_bfloat16 hx = __float2bfloat16(v.x), hy = __float2bfloat16(v.y);
    __nv_bfloat16 hz = __float2bfloat16(v.z), hw = __float2bfloat16(v.w);
    __nv_bfloat162 h01; h01.x = hx; h01.y = hy;
    __nv_bfloat162 h23; h23.x = hz; h23.y = hw;
    __nv_bfloat162 l01, l23;
    l01.x = __float2bfloat16(v.x - __bfloat162float(hx));
    l01.y = __float2bfloat16(v.y - __bfloat162float(hy));
    l23.x = __float2bfloat16(v.z - __bfloat162float(hz));
    l23.y = __float2bfloat16(v.w - __bfloat162float(hw));
    ((__nv_bfloat162*)hi)[i * 2 + 0] = h01;
    ((__nv_bfloat162*)hi)[i * 2 + 1] = h23;
    ((__nv_bfloat162*)lo)[i * 2 + 0] = l01;
    ((__nv_bfloat162*)lo)[i * 2 + 1] = l23;
}

__global__ void wtsplit_kernel(const float* __restrict__ W,
                               __nv_bfloat16* __restrict__ th,
                               __nv_bfloat16* __restrict__ tl, int N)
{
    int i = blockIdx.x * blockDim.x + threadIdx.x;
    int n = i >> 8, k = i & 255;
    float x = W[(size_t)k * N + n];
    __nv_bfloat16 h = __float2bfloat16(x);
    th[i] = h;
    tl[i] = __float2bfloat16(x - __bfloat162float(h));
}

// ---------------- SIMT fused GEMM (exact fp32 chains, f32x2-packed) ---------
// Each packed lane keeps its own sequential ascending-k fp32 FMA chain —
// bit-identical results to the scalar version (argmin-critical).
struct GArgs { const float* A; const float* W; const float* bias; float* C; int K; };

template<bool RELU, bool RESID>
__global__ __launch_bounds__(256, 3)
void gemm_kernel(GArgs g0, GArgs g1)
{
    const GArgs g = blockIdx.z ? g1 : g0;
    const int K = g.K;
    __shared__ float As[2][8][68];
    __shared__ float Bs[2][8][128];
    const int tid = threadIdx.x;
    const int tx = tid & 15, ty = tid >> 4;
    const int rowBase = blockIdx.y * 64;
    const int colBase = blockIdx.x * 128;

    const int ar = tid >> 1, ac4 = (tid & 1) * 4;
    const bool aAct = tid < 128;
    const float* Ap = aAct ? (g.A + (size_t)(rowBase + ar) * K + ac4) : g.A;
    const int br = tid >> 5, bc = (tid & 31) * 4;
    const float* Wp = g.W + (size_t)br * 256 + colBase + bc;
    const uint32_t bs0 = smem_u32(&Bs[0][br][bc]);
    const uint32_t bs1 = smem_u32(&Bs[1][br][bc]);

    uint64_t acc2[4][4];
#pragma unroll
    for (int i = 0; i < 4; i++)
#pragma unroll
        for (int j = 0; j < 4; j++) acc2[i][j] = 0ull;   // two +0.0f lanes

    float4 av = make_float4(0.f, 0.f, 0.f, 0.f);
    if (aAct) av = *(const float4*)Ap;
    cp16(bs0, Wp);
    asm volatile("cp.async.commit_group;");
    if (aAct) {
        As[0][ac4 + 0][ar] = av.x; As[0][ac4 + 1][ar] = av.y;
        As[0][ac4 + 2][ar] = av.z; As[0][ac4 + 3][ar] = av.w;
    }
    asm volatile("cp.async.wait_group 0;");
    __syncthreads();

    const int nIter = K >> 3;
    int buf = 0;
#pragma unroll 1
    for (int i = 0; i < nIter; i++) {
        const bool more = (i + 1 < nIter);
        if (more) {
            if (aAct) av = *(const float4*)(Ap + (size_t)(i + 1) * 8);
            cp16(buf ? bs0 : bs1, Wp + (size_t)(i + 1) * 8 * 256);
            asm volatile("cp.async.commit_group;");
        }
#pragma unroll
        for (int kk = 0; kk < 8; kk++) {
            float4 a4 = *(const float4*)&As[buf][kk][ty * 4];
            float4 b0 = *(const float4*)&Bs[buf][kk][tx * 4];
            float4 b1 = *(const float4*)&Bs[buf][kk][tx * 4 + 64];
            uint64_t bp[4] = {pack2f(b0.x, b0.y), pack2f(b0.z, b0.w),
                              pack2f(b1.x, b1.y), pack2f(b1.z, b1.w)};
            float a[4] = {a4.x, a4.y, a4.z, a4.w};
#pragma unroll
            for (int i2 = 0; i2 < 4; i2++) {
                uint64_t ai = splat2f(a[i2]);
#pragma unroll
                for (int j = 0; j < 4; j++) ffma2(acc2[i2][j], ai, bp[j]);
            }
        }
        if (more) {
            if (aAct) {
                int nb = buf ^ 1;
                As[nb][ac4 + 0][ar] = av.x; As[nb][ac4 + 1][ar] = av.y;
                As[nb][ac4 + 2][ar] = av.z; As[nb][ac4 + 3][ar] = av.w;
            }
            asm volatile("cp.async.wait_group 0;");
        }
        __syncthreads();
        buf ^= 1;
    }

#pragma unroll
    for (int i2 = 0; i2 < 4; i2++) {
        float accv[8];
#pragma unroll
        for (int j = 0; j < 4; j++)
            unpack2f(acc2[i2][j], accv[j * 2], accv[j * 2 + 1]);
        int row = rowBase + ty * 4 + i2;
        float* cr = g.C + (size_t)row * 256;
        const float* rr = RESID ? (g.A + (size_t)row * 256) : nullptr;
#pragma unroll
        for (int gg = 0; gg < 2; gg++) {
            int col = colBase + tx * 4 + gg * 64;
            float4 bb = *(const float4*)(g.bias + col);
            float4 v;
            v.x = accv[gg * 4 + 0] + bb.x;
            v.y = accv[gg * 4 + 1] + bb.y;
            v.z = accv[gg * 4 + 2] + bb.z;
            v.w = accv[gg * 4 + 3] + bb.w;
            if (RELU) {
                v.x = fmaxf(v.x, 0.f); v.y = fmaxf(v.y, 0.f);
                v.z = fmaxf(v.z, 0.f); v.w = fmaxf(v.w, 0.f);
            }
            if (RESID) {
                float4 rv = *(const float4*)(rr + col);
                v.x += rv.x; v.y += rv.y; v.z += rv.z; v.w += rv.w;
            }
            *(float4*)(cr + col) = v;
        }
    }
}

// =================== bf16 3-term mma core (round-11 proven, term-major) =====
#define MMA_CORE_BODY(AhP, AlP, BhP, BlP)                                       \
    const int lr = tid >> 1;                                                    \
    const int lc = (tid & 1) * 2;                                               \
    const __nv_bfloat16* Asrc[3] = {AhP, AhP, AlP};                             \
    const __nv_bfloat16* Bsrc[3] = {BhP, BlP, BhP};                             \
    float acc[4][4][4];                                                         \
    _Pragma("unroll")                                                           \
    for (int m = 0; m < 4; m++)                                                 \
        _Pragma("unroll")                                                       \
        for (int n = 0; n < 4; n++)                                             \
            _Pragma("unroll")                                                   \
            for (int c = 0; c < 4; c++) acc[m][n][c] = 0.f;                     \
    const uint32_t aAddr = smem_u32(&As[wr * 64 + (lane & 15)][(lane >> 4) * 8]); \
    const uint32_t bAddr = smem_u32(                                            \
        &Bs[wc * 32 + (lane & 7) + ((lane >> 4) & 1) * 8][((lane >> 3) & 1) * 8]); \
    uint4 ra0, ra1, rb0, rb1;                                                   \
    {                                                                           \
        const uint4* ga = (const uint4*)(Asrc[0] + (size_t)(rowBase + lr) * 256); \
        ra0 = ga[lc]; ra1 = ga[lc + 1];                                         \
        const uint4* gb = (const uint4*)(Bsrc[0] + (size_t)(colBase + lr) * 256); \
        rb0 = gb[lc]; rb1 = gb[lc + 1];                                         \
    }                                                                           \
    *(uint4*)&As[lr][lc * 8] = ra0; *(uint4*)&As[lr][lc * 8 + 8] = ra1;         \
    *(uint4*)&Bs[lr][lc * 8] = rb0; *(uint4*)&Bs[lr][lc * 8 + 8] = rb1;         \
    __syncthreads();                                                            \
    auto compute = [&]() {                                                      \
        _Pragma("unroll")                                                       \
        for (int ss = 0; ss < 2; ss++) {                                        \
            uint32_t af[4][4];                                                  \
            _Pragma("unroll")                                                   \
            for (int mt = 0; mt < 4; mt++) {                                    \
                uint32_t addr = aAddr + mt * 16 * 80 + ss * 32;                 \
                asm volatile(                                                   \
                    "ldmatrix.sync.aligned.m8n8.x4.shared.b16 {%0,%1,%2,%3}, [%4];" \
                    : "=r"(af[mt][0]), "=r"(af[mt][1]),                         \
                      "=r"(af[mt][2]), "=r"(af[mt][3]) : "r"(addr));            \
            }                                                                   \
            uint32_t bfr[2][4];                                                 \
            _Pragma("unroll")                                                   \
            for (int bp = 0; bp < 2; bp++) {                                    \
                uint32_t addr = bAddr + bp * 16 * 80 + ss * 32;                 \
                asm volatile(                                                   \
                    "ldmatrix.sync.aligned.m8n8.x4.shared.b16 {%0,%1,%2,%3}, [%4];" \
                    : "=r"(bfr[bp][0]), "=r"(bfr[bp][1]),                       \
                      "=r"(bfr[bp][2]), "=r"(bfr[bp][3]) : "r"(addr));          \
            }                                                                   \
            _Pragma("unroll")                                                   \
            for (int mt = 0; mt < 4; mt++)                                      \
                _Pragma("unroll")                                               \
                for (int nt = 0; nt < 4; nt++) {                                \
                    uint32_t b0 = bfr[nt >> 1][(nt & 1) * 2 + 0];               \
                    uint32_t b1 = bfr[nt >> 1][(nt & 1) * 2 + 1];               \
                    asm volatile(                                               \
                        "mma.sync.aligned.m16n8k16.row.col.f32.bf16.bf16.f32 "  \
                        "{%0,%1,%2,%3}, {%4,%5,%6,%7}, {%8,%9}, {%0,%1,%2,%3};" \
                        : "+f"(acc[mt][nt][0]), "+f"(acc[mt][nt][1]),           \
                          "+f"(acc[mt][nt][2]), "+f"(acc[mt][nt][3])            \
                        : "r"(af[mt][0]), "r"(af[mt][1]),                       \
                          "r"(af[mt][2]), "r"(af[mt][3]), "r"(b0), "r"(b1));    \
                }                                                               \
        }                                                                       \
    };                                                                          \
    for (int iter = 1; iter < 24; iter++) {                                     \
        const int t = iter >> 3, k0 = (iter & 7) << 5;                          \
        const uint4* ga = (const uint4*)(Asrc[t] + (size_t)(rowBase + lr) * 256 + k0); \
        ra0 = ga[lc]; ra1 = ga[lc + 1];                                         \
        const uint4* gb = (const uint4*)(Bsrc[t] + (size_t)(colBase + lr) * 256 + k0); \
        rb0 = gb[lc]; rb1 = gb[lc + 1];                                         \
        compute();                                                              \
        __syncthreads();                                                        \
        *(uint4*)&As[lr][lc * 8] = ra0; *(uint4*)&As[lr][lc * 8 + 8] = ra1;     \
        *(uint4*)&Bs[lr][lc * 8] = rb0; *(uint4*)&Bs[lr][lc * 8 + 8] = rb1;     \
        __syncthreads();                                                        \
    }                                                                           \
    compute();

// ---------------- decoder FINAL ----------------
__global__ __launch_bounds__(256, 2)
void mma_final_kernel(const __nv_bfloat16* __restrict__ Ah,
                      const __nv_bfloat16* __restrict__ Al,
                      const __nv_bfloat16* __restrict__ Bh,
                      const __nv_bfloat16* __restrict__ Bl,
                      const float* __restrict__ bias,
                      float* __restrict__ C0, float* __restrict__ C1,
                      int rowSplit, int N)
{
    __shared__ __align__(16) __nv_bfloat16 As[128][40];
    __shared__ __align__(16) __nv_bfloat16 Bs[128][40];
    const int tid = threadIdx.x;
    const int wid = tid >> 5, lane = tid & 31;
    const int wr = wid >> 2, wc = wid & 3;
    const int rowBase = blockIdx.y * 128;
    const int colBase = blockIdx.x * 128;

    MMA_CORE_BODY(Ah, Al, Bh, Bl)

#pragma unroll
    for (int mt = 0; mt < 4; mt++) {
        int row0 = rowBase + wr * 64 + mt * 16 + (lane >> 2);
#pragma unroll
        for (int h = 0; h < 2; h++) {
            int row = row0 + h * 8;
            float* cr = (row < rowSplit) ? (C0 + (size_t)row * N)
                                         : (C1 + (size_t)(row - rowSplit) * N);
#pragma unroll
            for (int nt = 0; nt < 4; nt++) {
                int col = colBase + wc * 32 + nt * 8 + (lane & 3) * 2;
                float2 bb = *(const float2*)(bias + col);
                float2 v;
                v.x = acc[mt][nt][h * 2 + 0] + bb.x;
                v.y = acc[mt][nt][h * 2 + 1] + bb.y;
                *(float2*)(cr + col) = v;
            }
        }
    }
}

// ---------------- decoder RES block ----------------
template<bool WF32>
__global__ __launch_bounds__(256, 2)
void mma_res_kernel(const float* __restrict__ Af,
                    const __nv_bfloat16* __restrict__ Ah,
                    const __nv_bfloat16* __restrict__ Al,
                    const __nv_bfloat16* __restrict__ Bh,
                    const __nv_bfloat16* __restrict__ Bl,
                    const float* __restrict__ bias,
                    float* __restrict__ Cf,
                    __nv_bfloat16* __restrict__ Ch,
                    __nv_bfloat16* __restrict__ Cl)
{
    __shared__ __align__(16) __nv_bfloat16 As[128][40];
    __shared__ __align__(16) __nv_bfloat16 Bs[128][40];
    const int tid = threadIdx.x;
    const int wid = tid >> 5, lane = tid & 31;
    const int wr = wid >> 2, wc = wid & 3;
    const int rowBase = blockIdx.y * 128;
    const int colBase = blockIdx.x * 128;

    MMA_CORE_BODY(Ah, Al, Bh, Bl)

#pragma unroll
    for (int mt = 0; mt < 4; mt++) {
        int row0 = rowBase + wr * 64 + mt * 16 + (lane >> 2);
#pragma unroll
        for (int h = 0; h < 2; h++) {
            int row = row0 + h * 8;
#pragma unroll
            for (int nt = 0; nt < 4; nt++) {
                int col = colBase + wc * 32 + nt * 8 + (lane & 3) * 2;
                size_t off = (size_t)row * 256 + col;
                float2 bb = *(const float2*)(bias + col);
                float2 rv = *(const float2*)(Af + off);
                float vx = rv.x + fmaxf(acc[mt][nt][h * 2 + 0] + bb.x, 0.f);
                float vy = rv.y + fmaxf(acc[mt][nt][h * 2 + 1] + bb.y, 0.f);
                if (WF32) { float2 o; o.x = vx; o.y = vy; *(float2*)(Cf + off) = o; }
                __nv_bfloat162 hh, ll;
                hh.x = __float2bfloat16(vx); hh.y = __float2bfloat16(vy);
                ll.x = __float2bfloat16(vx - __bfloat162float(hh.x));
                ll.y = __float2bfloat16(vy - __bfloat162float(hh.y));
                *(__nv_bfloat162*)(Ch + off) = hh;
                *(__nv_bfloat162*)(Cl + off) = ll;
            }
        }
    }
}

// ---------------- VQ phase 1 ----------------
__global__ __launch_bounds__(256, 2)
void vq_mma_kernel()
{
    __shared__ __align__(16) __nv_bfloat16 As[128][40];
    __shared__ __align__(16) __nv_bfloat16 Bs[128][40];
    const int tid = threadIdx.x;
    const int wid = tid >> 5, lane = tid & 31;
    const int wr = wid >> 2, wc = wid & 3;
    const int rowBase = blockIdx.y * 128;
    const int colBase = blockIdx.x * 128;
    const int bz = blockIdx.z;
    const __nv_bfloat16* Zh = bz ? g_zh_b : g_zh_a;
    const __nv_bfloat16* Zl = bz ? g_zl_b : g_zl_a;
    short* Q = bz ? g_q_b : g_q_a;
    int* qmax = bz ? g_qmax_b : g_qmax_a;

    MMA_CORE_BODY(Zh, Zl, g_eh, g_el)

#pragma unroll
    for (int mt = 0; mt < 4; mt++) {
        int row0 = rowBase + wr * 64 + mt * 16 + (lane >> 2);
#pragma unroll
        for (int h = 0; h < 2; h++) {
            int row = row0 + h * 8;
            int mq = INT_MIN;
#pragma unroll
            for (int nt = 0; nt < 4; nt++) {
                int col = colBase + wc * 32 + nt * 8 + (lane & 3) * 2;
                float t0 = 2.f * acc[mt][nt][h * 2 + 0];
                float t1 = 2.f * acc[mt][nt][h * 2 + 1];
                int q0 = __float2int_rn(t0 * 524288.f);
                int q1 = __float2int_rn(t1 * 524288.f);
                q0 = max(-32000, min(32000, q0));
                q1 = max(-32000, min(32000, q1));
                mq = max(mq, max(q0, q1));
                short2 sv; sv.x = (short)q0; sv.y = (short)q1;
                *(short2*)(Q + (size_t)row * NCODE + col) = sv;
            }
            mq = max(mq, __shfl_xor_sync(0xffffffffu, mq, 1));
            mq = max(mq, __shfl_xor_sync(0xffffffffu, mq, 2));
            if ((lane & 3) == 0) atomicMax(&qmax[row], mq);
        }
    }
}

// ---------------- VQ phase 2 (exact serial fp32 chain) ----------------
__global__ __launch_bounds__(256)
void vq_select_kernel(const float* __restrict__ Z0, const float* __restrict__ Z1,
                      const float* __restrict__ E)
{
    const int row = blockIdx.x, bz = blockIdx.y;
    const int tid = threadIdx.x;
    const float* Zr = (bz ? Z1 : Z0) + (size_t)row * DLAT;
    const short* Q = (bz ? g_q_b : g_q_a) + (size_t)row * NCODE;
    const int thr = (bz ? g_qmax_b : g_qmax_a)[row] - 48;
    const double zz = (bz ? g_zz_b : g_zz_a)[row];

    __shared__ float zs[DLAT];
    __shared__ int cnt;
    __shared__ int cand[128];
    __shared__ unsigned long long best;
    zs[tid] = Zr[tid];
    if (tid == 0) { cnt = 0; best = ~0ull; }
    __syncthreads();

    const short2* Q2 = (const short2*)Q;
#pragma unroll
    for (int it = 0; it < 16; it++) {
        int i2 = tid + it * 256;
        short2 v = Q2[i2];
        if (v.x >= thr) { int p = atomicAdd(&cnt, 1); if (p < 128) cand[p] = i2 * 2; }
        if (v.y >= thr) { int p = atomicAdd(&cnt, 1); if (p < 128) cand[p] = i2 * 2 + 1; }
    }
    __syncthreads();

    int n = min(cnt, 128);
    if (tid < n) {
        int c = cand[tid];
        const float* e = E + (size_t)c * DLAT;
        float accv = 0.f;
#pragma unroll 8
        for (int k = 0; k < DLAT; k++) accv = fmaf(zs[k], e[k], accv);
        double t = 2.0 * (double)accv;
        double d = zz - t;
        long long db = __double_as_longlong(d);
        int ebias = (int)((db >> 52) & 0x7ff);
        double cell = __longlong_as_double((long long)(ebias - 23) << 52);
        double r = cell * rint(t / cell);
        float rf = (float)r;
        unsigned u = __float_as_uint(rf);
        u = (u & 0x80000000u) ? ~u : (u | 0x80000000u);
        unsigned long long key = ((unsigned long long)(~u) << 32) | (unsigned)c;
        atomicMin(&best, key);
    }
    __syncthreads();
    if (tid == 0) (bz ? g_win_b : g_win_a)[row] = (int)(best & 0xffffffffull);
}

// ---------------- VQ finalize ----------------
__global__ void vq_finalize_kernel(const float* __restrict__ Z0, const float* __restrict__ Z1,
                                   const float* __restrict__ E,
                                   float* __restrict__ zq0, float* __restrict__ zq1,
                                   float* __restrict__ ls0, float* __restrict__ ls1)
{
    const int bz = blockIdx.y;
    const float* Z = bz ? Z1 : Z0;
    float* zq = bz ? zq1 : zq0;
    float* loss = bz ? ls1 : ls0;
    int row  = blockIdx.x * 8 + (threadIdx.x >> 5);
    int lane = threadIdx.x & 31;
    int idx  = (bz ? g_win_b : g_win_a)[row];
    const float4* zp = reinterpret_cast<const float4*>(Z) + (size_t)row * (DLAT / 4);
    const float4* ep = reinterpret_cast<const float4*>(E) + (size_t)idx * (DLAT / 4);
    float4* qp = reinterpret_cast<float4*>(zq) + (size_t)row * (DLAT / 4);
    size_t srow = ((size_t)bz * BATCH + row) * DLAT;
    float s = 0.f;
#pragma unroll
    for (int t = 0; t < 2; t++) {
        float4 z = zp[lane + 32 * t], e = ep[lane + 32 * t];
        float dx = e.x - z.x, dy = e.y - z.y, dz = e.z - z.z, dw = e.w - z.w;
        float4 o;
        o.x = z.x + dx; o.y = z.y + dy; o.z = z.z + dz; o.w = z.w + dw;
        qp[lane + 32 * t] = o;
        float vv[4] = {o.x, o.y, o.z, o.w};
#pragma unroll
        for (int p = 0; p < 2; p++) {
            __nv_bfloat162 hh, ll;
            hh.x = __float2bfloat16(vv[p * 2 + 0]);
            hh.y = __float2bfloat16(vv[p * 2 + 1]);
            ll.x = __float2bfloat16(vv[p * 2 + 0] - __bfloat162float(hh.x));
            ll.y = __float2bfloat16(vv[p * 2 + 1] - __bfloat162float(hh.y));
            size_t eo = srow + (lane + 32 * t) * 4 + p * 2;
            *(__nv_bfloat162*)(g_zqh + eo) = hh;
            *(__nv_bfloat162*)(g_zql + eo) = ll;
        }
        s += dx * dx + dy * dy + dz * dz + dw * dw;
    }
#pragma unroll
    for (int o = 16; o; o >>= 1) s += __shfl_down_sync(0xffffffffu, s, o);
    if (lane == 0) loss[row] = s + BETA_F * s;
}

// ---------------- launcher ----------------
extern "C" void kernel_launch(void* const* d_in, const int* in_sizes, int n_in,
                              void* d_out, int out_size)
{
    const float* x_a      = (const float*)d_in[0];
    const float* x_b      = (const float*)d_in[1];
    const float* enc_a_w  = (const float*)d_in[2];
    const float* enc_a_b  = (const float*)d_in[3];
    const float* enc_a_rw = (const float*)d_in[4];
    const float* enc_a_rb = (const float*)d_in[5];
    const float* enc_b_w  = (const float*)d_in[6];
    const float* enc_b_b  = (const float*)d_in[7];
    const float* enc_b_rw = (const float*)d_in[8];
    const float* enc_b_rb = (const float*)d_in[9];
    const float* dec_a_rw = (const float*)d_in[10];
    const float* dec_a_rb = (const float*)d_in[11];
    const float* dec_a_w  = (const float*)d_in[12];
    const float* dec_a_b  = (const float*)d_in[13];
    const float* dec_b_rw = (const float*)d_in[14];
    const float* dec_b_rb = (const float*)d_in[15];
    const float* dec_b_w  = (const float*)d_in[16];
    const float* dec_b_b  = (const float*)d_in[17];
    const float* codebook = (const float*)d_in[18];

    float *ze_a0, *ze_a1, *ze_b0, *ze_b1, *h1a, *h1b;
    double *zz_a, *zz_b;
    __nv_bfloat16 *zh_a, *zl_a, *zh_b, *zl_b, *eh, *el, *zqh, *zql;
    __nv_bfloat16 *s1h_a, *s1l_a, *s0h_a, *s0l_a, *s1h_b, *s1l_b, *s0h_b, *s0l_b;
    __nv_bfloat16 *wth_a, *wtl_a, *wth_b, *wtl_b;
    __nv_bfloat16 *rwth_a, *rwtl_a, *rwth_b, *rwtl_b;
    cudaGetSymbolAddress((void**)&ze_a0, g_ze_a0);
    cudaGetSymbolAddress((void**)&ze_a1, g_ze_a1);
    cudaGetSymbolAddress((void**)&ze_b0, g_ze_b0);
    cudaGetSymbolAddress((void**)&ze_b1, g_ze_b1);
    cudaGetSymbolAddress((void**)&h1a, g_h1a);
    cudaGetSymbolAddress((void**)&h1b, g_h1b);
    cudaGetSymbolAddress((void**)&zz_a, g_zz_a);
    cudaGetSymbolAddress((void**)&zz_b, g_zz_b);
    cudaGetSymbolAddress((void**)&zh_a, g_zh_a);
    cudaGetSymbolAddress((void**)&zl_a, g_zl_a);
    cudaGetSymbolAddress((void**)&zh_b, g_zh_b);
    cudaGetSymbolAddress((void**)&zl_b, g_zl_b);
    cudaGetSymbolAddress((void**)&eh, g_eh);
    cudaGetSymbolAddress((void**)&el, g_el);
    cudaGetSymbolAddress((void**)&zqh, g_zqh);
    cudaGetSymbolAddress((void**)&zql, g_zql);
    cudaGetSymbolAddress((void**)&s1h_a, g_s1h_a);
    cudaGetSymbolAddress((void**)&s1l_a, g_s1l_a);
    cudaGetSymbolAddress((void**)&s0h_a, g_s0h_a);
    cudaGetSymbolAddress((void**)&s0l_a, g_s0l_a);
    cudaGetSymbolAddress((void**)&s1h_b, g_s1h_b);
    cudaGetSymbolAddress((void**)&s1l_b, g_s1l_b);
    cudaGetSymbolAddress((void**)&s0h_b, g_s0h_b);
    cudaGetSymbolAddress((void**)&s0l_b, g_s0l_b);
    cudaGetSymbolAddress((void**)&wth_a, g_wth_a);
    cudaGetSymbolAddress((void**)&wtl_a, g_wtl_a);
    cudaGetSymbolAddress((void**)&wth_b, g_wth_b);
    cudaGetSymbolAddress((void**)&wtl_b, g_wtl_b);
    cudaGetSymbolAddress((void**)&rwth_a, g_rwth_a);
    cudaGetSymbolAddress((void**)&rwtl_a, g_rwtl_a);
    cudaGetSymbolAddress((void**)&rwth_b, g_rwth_b);
    cudaGetSymbolAddress((void**)&rwtl_b, g_rwtl_b);

    float* out = (float*)d_out;
    const size_t OFF_ZA = 0;
    const size_t OFF_ZB = (size_t)BATCH * DLAT;
    const size_t OFF_LA = 2 * OFF_ZB;
    const size_t OFF_LB = OFF_LA + BATCH;
    const size_t OFF_RA = OFF_LB + BATCH;
    const size_t OFF_RB = OFF_RA + (size_t)BATCH * DINA;
    const size_t OFF_XA = OFF_RB + (size_t)BATCH * DINB;
    const size_t OFF_XB = OFF_XA + (size_t)BATCH * DINA;

    init_qmax_kernel<<<(BATCH + 255) / 256, 256>>>();
    wtsplit_kernel<<<DINA, 256>>>(dec_a_w, wth_a, wtl_a, DINA);
    wtsplit_kernel<<<DINB, 256>>>(dec_b_w, wth_b, wtl_b, DINB);
    wtsplit_kernel<<<DLAT, 256>>>(dec_a_rw, rwth_a, rwtl_a, DLAT);
    wtsplit_kernel<<<DLAT, 256>>>(dec_a_rw + DLAT * DLAT, rwth_a + DLAT * DLAT,
                                  rwtl_a + DLAT * DLAT, DLAT);
    wtsplit_kernel<<<DLAT, 256>>>(dec_b_rw, rwth_b, rwtl_b, DLAT);
    wtsplit_kernel<<<DLAT, 256>>>(dec_b_rw + DLAT * DLAT, rwth_b + DLAT * DLAT,
                                  rwtl_b + DLAT * DLAT, DLAT);
    split1_kernel<<<(NCODE * DLAT / 4 + 255) / 256, 256>>>(codebook, eh, el,
                                                           NCODE * DLAT / 4);

    // encoders (exact fp32 chains; f32x2-packed, bit-identical)
    gemm_kernel<true, false><<<dim3(2, BATCH / 64, 2), 256>>>(
        GArgs{x_a, enc_a_w, enc_a_b, ze_a0, DINA},
        GArgs{x_b, enc_b_w, enc_b_b, ze_b0, DINB});
    gemm_kernel<true, true><<<dim3(2, BATCH / 64, 2), 256>>>(
        GArgs{ze_a0, enc_a_rw, enc_a_rb, ze_a1, DLAT},
        GArgs{ze_b0, enc_b_rw, enc_b_rb, ze_b1, DLAT});
    gemm_kernel<true, true><<<dim3(2, BATCH / 64, 2), 256>>>(
        GArgs{ze_a1, enc_a_rw + DLAT * DLAT, enc_a_rb + DLAT, ze_a0, DLAT},
        GArgs{ze_b1, enc_b_rw + DLAT * DLAT, enc_b_rb + DLAT, ze_b0, DLAT});

    zz_kernel<<<dim3(BATCH / 8, 2), 256>>>(ze_a0, ze_b0, zz_a, zz_b);
    split1_kernel<<<(BATCH * DLAT / 4 + 255) / 256, 256>>>(ze_a0, zh_a, zl_a,
                                                           BATCH * DLAT / 4);
    split1_kernel<<<(BATCH * DLAT / 4 + 255) / 256, 256>>>(ze_b0, zh_b, zl_b,
                                                           BATCH * DLAT / 4);

    vq_mma_kernel<<<dim3(NCODE / 128, BATCH / 128, 2), 256>>>();
    vq_select_kernel<<<dim3(BATCH, 2), 256>>>(ze_a0, ze_b0, codebook);

    vq_finalize_kernel<<<dim3(BATCH / 8, 2), 256>>>(
        ze_a0, ze_b0, codebook,
        out + OFF_ZA, out + OFF_ZB, out + OFF_LA, out + OFF_LB);

    const float* Zq = out;

    mma_res_kernel<true><<<dim3(2, 2 * BATCH / 128), 256>>>(
        Zq, zqh, zql, rwth_a, rwtl_a, dec_a_rb, h1a, s1h_a, s1l_a);
    mma_res_kernel<true><<<dim3(2, 2 * BATCH / 128), 256>>>(
        Zq, zqh, zql, rwth_b, rwtl_b, dec_b_rb, h1b, s1h_b, s1l_b);
    mma_res_kernel<false><<<dim3(2, 2 * BATCH / 128), 256>>>(
        h1a, s1h_a, s1l_a, rwth_a + DLAT * DLAT, rwtl_a + DLAT * DLAT,
        dec_a_rb + DLAT, nullptr, s0h_a, s0l_a);
    mma_res_kernel<false><<<dim3(2, 2 * BATCH / 128), 256>>>(
        h1b, s1h_b, s1l_b, rwth_b + DLAT * DLAT, rwtl_b + DLAT * DLAT,
        dec_b_rb + DLAT, nullptr, s0h_b, s0l_b);

    mma_final_kernel<<<dim3(DINA / 128, 2 * BATCH / 128), 256>>>(
        s0h_a, s0l_a, wth_a, wtl_a, dec_a_b,
        out + OFF_RA, out + OFF_XA, BATCH, DINA);
    mma_final_kernel<<<dim3(DINB / 128, 2 * BATCH / 128), 256>>>(
        s0h_b, s0l_b, wth_b, wtl_b, dec_b_b,
        out + OFF_XB, out + OFF_RB, BATCH, DINB);
}

// round 14
// speedup vs baseline: 1.2590x; 1.2590x over previous
#include <cuda_runtime.h>
#include <cuda_bf16.h>
#include <cstdint>
#include <climits>

#define BATCH   8192
#define DINA    4096
#define DINB    2048
#define DLAT    256
#define NCODE   8192
#define BETA_F  0.25f
#define QTHR    160      // select margin in int16 cells (3e-4 in t; 3x worst-case err)

// ---------------- scratch (static __device__ — no allocation) ----------------
__device__ float g_ze_a0[BATCH * DLAT];
__device__ float g_ze_a1[BATCH * DLAT];
__device__ float g_ze_b0[BATCH * DLAT];
__device__ float g_ze_b1[BATCH * DLAT];
__device__ float g_h1a[2 * BATCH * DLAT];
__device__ float g_h1b[2 * BATCH * DLAT];
__device__ double g_zz_a[BATCH];
__device__ double g_zz_b[BATCH];
__device__ int g_qmax_a[BATCH];
__device__ int g_qmax_b[BATCH];
__device__ int g_win_a[BATCH];
__device__ int g_win_b[BATCH];
__device__ short g_q_a[(size_t)BATCH * NCODE];
__device__ short g_q_b[(size_t)BATCH * NCODE];
// bf16 splits
__device__ __nv_bfloat16 g_zh_a[BATCH * DLAT];
__device__ __nv_bfloat16 g_zl_a[BATCH * DLAT];
__device__ __nv_bfloat16 g_zh_b[BATCH * DLAT];
__device__ __nv_bfloat16 g_zl_b[BATCH * DLAT];
__device__ __nv_bfloat16 g_eh[NCODE * DLAT];
__device__ __nv_bfloat16 g_el[NCODE * DLAT];
__device__ __nv_bfloat16 g_zqh[2 * BATCH * DLAT];
__device__ __nv_bfloat16 g_zql[2 * BATCH * DLAT];
__device__ __nv_bfloat16 g_s1h_a[2 * BATCH * DLAT];
__device__ __nv_bfloat16 g_s1l_a[2 * BATCH * DLAT];
__device__ __nv_bfloat16 g_s0h_a[2 * BATCH * DLAT];
__device__ __nv_bfloat16 g_s0l_a[2 * BATCH * DLAT];
__device__ __nv_bfloat16 g_s1h_b[2 * BATCH * DLAT];
__device__ __nv_bfloat16 g_s1l_b[2 * BATCH * DLAT];
__device__ __nv_bfloat16 g_s0h_b[2 * BATCH * DLAT];
__device__ __nv_bfloat16 g_s0l_b[2 * BATCH * DLAT];
__device__ __nv_bfloat16 g_wth_a[DINA * DLAT];
__device__ __nv_bfloat16 g_wtl_a[DINA * DLAT];
__device__ __nv_bfloat16 g_wth_b[DINB * DLAT];
__device__ __nv_bfloat16 g_wtl_b[DINB * DLAT];
__device__ __nv_bfloat16 g_rwth_a[2 * DLAT * DLAT];
__device__ __nv_bfloat16 g_rwtl_a[2 * DLAT * DLAT];
__device__ __nv_bfloat16 g_rwth_b[2 * DLAT * DLAT];
__device__ __nv_bfloat16 g_rwtl_b[2 * DLAT * DLAT];

__device__ __forceinline__ uint32_t smem_u32(const void* p) {
    uint32_t a;
    asm("{ .reg .u64 t; cvta.to.shared.u64 t, %1; cvt.u32.u64 %0, t; }"
        : "=r"(a) : "l"(p));
    return a;
}
__device__ __forceinline__ void cp16(uint32_t s, const void* g) {
    asm volatile("cp.async.cg.shared.global [%0], [%1], 16;" :: "r"(s), "l"(g));
}

// ---------------- small helpers ----------------
__global__ void init_qmax_kernel() {
    int i = blockIdx.x * blockDim.x + threadIdx.x;
    if (i < BATCH) { g_qmax_a[i] = INT_MIN; g_qmax_b[i] = INT_MIN; }
}

__global__ void zz_kernel(const float* __restrict__ Z0, const float* __restrict__ Z1,
                          double* __restrict__ zz0, double* __restrict__ zz1) {
    const float* Z = blockIdx.y ? Z1 : Z0;
    double* zz = blockIdx.y ? zz1 : zz0;
    int row  = blockIdx.x * 8 + (threadIdx.x >> 5);
    int lane = threadIdx.x & 31;
    const float4* zp = reinterpret_cast<const float4*>(Z) + (size_t)row * (DLAT / 4);
    double s = 0.0;
#pragma unroll
    for (int t = 0; t < 2; t++) {
        float4 v = zp[lane + 32 * t];
        s += (double)v.x * v.x + (double)v.y * v.y
           + (double)v.z * v.z + (double)v.w * v.w;
    }
#pragma unroll
    for (int o = 16; o; o >>= 1) s += __shfl_down_sync(0xffffffffu, s, o);
    if (lane == 0) zz[row] = s;
}

__global__ void split1_kernel(const float* __restrict__ x,
                              __nv_bfloat16* __restrict__ hi,
                              __nv_bfloat16* __restrict__ lo, int n4)
{
    int i = blockIdx.x * blockDim.x + threadIdx.x;
    if (i >= n4) return;
    float4 v = ((const float4*)x)[i];
    __nv_bfloat16 hx = __float2bfloat16(v.x), hy = __float2bfloat16(v.y);
    __nv_bfloat16 hz = __float2bfloat16(v.z), hw = __float2bfloat16(v.w);
    __nv_bfloat162 h01; h01.x = hx; h01.y = hy;
    __nv_bfloat162 h23; h23.x = hz; h23.y = hw;
    __nv_bfloat162 l01, l23;
    l01.x = __float2bfloat16(v.x - __bfloat162float(hx));
    l01.y = __float2bfloat16(v.y - __bfloat162float(hy));
    l23.x = __float2bfloat16(v.z - __bfloat162float(hz));
    l23.y = __float2bfloat16(v.w - __bfloat162float(hw));
    ((__nv_bfloat162*)hi)[i * 2 + 0] = h01;
    ((__nv_bfloat162*)hi)[i * 2 + 1] = h23;
    ((__nv_bfloat162*)lo)[i * 2 + 0] = l01;
    ((__nv_bfloat162*)lo)[i * 2 + 1] = l23;
}

__global__ void wtsplit_kernel(const float* __restrict__ W,
                               __nv_bfloat16* __restrict__ th,
                               __nv_bfloat16* __restrict__ tl, int N)
{
    int i = blockIdx.x * blockDim.x + threadIdx.x;
    int n = i >> 8, k = i & 255;
    float x = W[(size_t)k * N + n];
    __nv_bfloat16 h = __float2bfloat16(x);
    th[i] = h;
    tl[i] = __float2bfloat16(x - __bfloat162float(h));
}

// ---------------- SIMT fused GEMM (exact scalar fp32 chains — encoders) -----
struct GArgs { const float* A; const float* W; const float* bias; float* C; int K; };

template<bool RELU, bool RESID>
__global__ __launch_bounds__(256, 3)
void gemm_kernel(GArgs g0, GArgs g1)
{
    const GArgs g = blockIdx.z ? g1 : g0;
    const int K = g.K;
    __shared__ float As[2][8][68];
    __shared__ float Bs[2][8][128];
    const int tid = threadIdx.x;
    const int tx = tid & 15, ty = tid >> 4;
    const int rowBase = blockIdx.y * 64;
    const int colBase = blockIdx.x * 128;

    const int ar = tid >> 1, ac4 = (tid & 1) * 4;
    const bool aAct = tid < 128;
    const float* Ap = aAct ? (g.A + (size_t)(rowBase + ar) * K + ac4) : g.A;
    const int br = tid >> 5, bc = (tid & 31) * 4;
    const float* Wp = g.W + (size_t)br * 256 + colBase + bc;
    const uint32_t bs0 = smem_u32(&Bs[0][br][bc]);
    const uint32_t bs1 = smem_u32(&Bs[1][br][bc]);

    float acc[4][8];
#pragma unroll
    for (int i = 0; i < 4; i++)
#pragma unroll
        for (int j = 0; j < 8; j++) acc[i][j] = 0.f;

    float4 av = make_float4(0.f, 0.f, 0.f, 0.f);
    if (aAct) av = *(const float4*)Ap;
    cp16(bs0, Wp);
    asm volatile("cp.async.commit_group;");
    if (aAct) {
        As[0][ac4 + 0][ar] = av.x; As[0][ac4 + 1][ar] = av.y;
        As[0][ac4 + 2][ar] = av.z; As[0][ac4 + 3][ar] = av.w;
    }
    asm volatile("cp.async.wait_group 0;");
    __syncthreads();

    const int nIter = K >> 3;
    int buf = 0;
#pragma unroll 1
    for (int i = 0; i < nIter; i++) {
        const bool more = (i + 1 < nIter);
        if (more) {
            if (aAct) av = *(const float4*)(Ap + (size_t)(i + 1) * 8);
            cp16(buf ? bs0 : bs1, Wp + (size_t)(i + 1) * 8 * 256);
            asm volatile("cp.async.commit_group;");
        }
#pragma unroll
        for (int kk = 0; kk < 8; kk++) {
            float4 a4 = *(const float4*)&As[buf][kk][ty * 4];
            float4 b0 = *(const float4*)&Bs[buf][kk][tx * 4];
            float4 b1 = *(const float4*)&Bs[buf][kk][tx * 4 + 64];
            float a[4] = {a4.x, a4.y, a4.z, a4.w};
            float b[8] = {b0.x, b0.y, b0.z, b0.w, b1.x, b1.y, b1.z, b1.w};
#pragma unroll
            for (int i2 = 0; i2 < 4; i2++)
#pragma unroll
                for (int j = 0; j < 8; j++)
                    acc[i2][j] = fmaf(a[i2], b[j], acc[i2][j]);
        }
        if (more) {
            if (aAct) {
                int nb = buf ^ 1;
                As[nb][ac4 + 0][ar] = av.x; As[nb][ac4 + 1][ar] = av.y;
                As[nb][ac4 + 2][ar] = av.z; As[nb][ac4 + 3][ar] = av.w;
            }
            asm volatile("cp.async.wait_group 0;");
        }
        __syncthreads();
        buf ^= 1;
    }

#pragma unroll
    for (int i2 = 0; i2 < 4; i2++) {
        int row = rowBase + ty * 4 + i2;
        float* cr = g.C + (size_t)row * 256;
        const float* rr = RESID ? (g.A + (size_t)row * 256) : nullptr;
#pragma unroll
        for (int gg = 0; gg < 2; gg++) {
            int col = colBase + tx * 4 + gg * 64;
            float4 bb = *(const float4*)(g.bias + col);
            float4 v;
            v.x = acc[i2][gg * 4 + 0] + bb.x;
            v.y = acc[i2][gg * 4 + 1] + bb.y;
            v.z = acc[i2][gg * 4 + 2] + bb.z;
            v.w = acc[i2][gg * 4 + 3] + bb.w;
            if (RELU) {
                v.x = fmaxf(v.x, 0.f); v.y = fmaxf(v.y, 0.f);
                v.z = fmaxf(v.z, 0.f); v.w = fmaxf(v.w, 0.f);
            }
            if (RESID) {
                float4 rv = *(const float4*)(rr + col);
                v.x += rv.x; v.y += rv.y; v.z += rv.z; v.w += rv.w;
            }
            *(float4*)(cr + col) = v;
        }
    }
}

// =================== bf16 mma core (term-major, proven; ITERS param) ========
// ITERS=24: 3-term (AhBh, AhBl, AlBh). ITERS=8: 1-term (AhBh only).
#define MMA_CORE_BODY(ITERS, AhP, AlP, BhP, BlP)                                \
    const int lr = tid >> 1;                                                    \
    const int lc = (tid & 1) * 2;                                               \
    const __nv_bfloat16* Asrc[3] = {AhP, AhP, AlP};                             \
    const __nv_bfloat16* Bsrc[3] = {BhP, BlP, BhP};                             \
    float acc[4][4][4];                                                         \
    _Pragma("unroll")                                                           \
    for (int m = 0; m < 4; m++)                                                 \
        _Pragma("unroll")                                                       \
        for (int n = 0; n < 4; n++)                                             \
            _Pragma("unroll")                                                   \
            for (int c = 0; c < 4; c++) acc[m][n][c] = 0.f;                     \
    const uint32_t aAddr = smem_u32(&As[wr * 64 + (lane & 15)][(lane >> 4) * 8]); \
    const uint32_t bAddr = smem_u32(                                            \
        &Bs[wc * 32 + (lane & 7) + ((lane >> 4) & 1) * 8][((lane >> 3) & 1) * 8]); \
    uint4 ra0, ra1, rb0, rb1;                                                   \
    {                                                                           \
        const uint4* ga = (const uint4*)(Asrc[0] + (size_t)(rowBase + lr) * 256); \
        ra0 = ga[lc]; ra1 = ga[lc + 1];                                         \
        const uint4* gb = (const uint4*)(Bsrc[0] + (size_t)(colBase + lr) * 256); \
        rb0 = gb[lc]; rb1 = gb[lc + 1];                                         \
    }                                                                           \
    *(uint4*)&As[lr][lc * 8] = ra0; *(uint4*)&As[lr][lc * 8 + 8] = ra1;         \
    *(uint4*)&Bs[lr][lc * 8] = rb0; *(uint4*)&Bs[lr][lc * 8 + 8] = rb1;         \
    __syncthreads();                                                            \
    auto compute = [&]() {                                                      \
        _Pragma("unroll")                                                       \
        for (int ss = 0; ss < 2; ss++) {                                        \
            uint32_t af[4][4];                                                  \
            _Pragma("unroll")                                                   \
            for (int mt = 0; mt < 4; mt++) {                                    \
                uint32_t addr = aAddr + mt * 16 * 80 + ss * 32;                 \
                asm volatile(                                                   \
                    "ldmatrix.sync.aligned.m8n8.x4.shared.b16 {%0,%1,%2,%3}, [%4];" \
                    : "=r"(af[mt][0]), "=r"(af[mt][1]),                         \
                      "=r"(af[mt][2]), "=r"(af[mt][3]) : "r"(addr));            \
            }                                                                   \
            uint32_t bfr[2][4];                                                 \
            _Pragma("unroll")                                                   \
            for (int bp = 0; bp < 2; bp++) {                                    \
                uint32_t addr = bAddr + bp * 16 * 80 + ss * 32;                 \
                asm volatile(                                                   \
                    "ldmatrix.sync.aligned.m8n8.x4.shared.b16 {%0,%1,%2,%3}, [%4];" \
                    : "=r"(bfr[bp][0]), "=r"(bfr[bp][1]),                       \
                      "=r"(bfr[bp][2]), "=r"(bfr[bp][3]) : "r"(addr));          \
            }                                                                   \
            _Pragma("unroll")                                                   \
            for (int mt = 0; mt < 4; mt++)                                      \
                _Pragma("unroll")                                               \
                for (int nt = 0; nt < 4; nt++) {                                \
                    uint32_t b0 = bfr[nt >> 1][(nt & 1) * 2 + 0];               \
                    uint32_t b1 = bfr[nt >> 1][(nt & 1) * 2 + 1];               \
                    asm volatile(                                               \
                        "mma.sync.aligned.m16n8k16.row.col.f32.bf16.bf16.f32 "  \
                        "{%0,%1,%2,%3}, {%4,%5,%6,%7}, {%8,%9}, {%0,%1,%2,%3};" \
                        : "+f"(acc[mt][nt][0]), "+f"(acc[mt][nt][1]),           \
                          "+f"(acc[mt][nt][2]), "+f"(acc[mt][nt][3])            \
                        : "r"(af[mt][0]), "r"(af[mt][1]),                       \
                          "r"(af[mt][2]), "r"(af[mt][3]), "r"(b0), "r"(b1));    \
                }                                                               \
        }                                                                       \
    };                                                                          \
    for (int iter = 1; iter < (ITERS); iter++) {                                \
        const int t = iter >> 3, k0 = (iter & 7) << 5;                          \
        const uint4* ga = (const uint4*)(Asrc[t] + (size_t)(rowBase + lr) * 256 + k0); \
        ra0 = ga[lc]; ra1 = ga[lc + 1];                                         \
        const uint4* gb = (const uint4*)(Bsrc[t] + (size_t)(colBase + lr) * 256 + k0); \
        rb0 = gb[lc]; rb1 = gb[lc + 1];                                         \
        compute();                                                              \
        __syncthreads();                                                        \
        *(uint4*)&As[lr][lc * 8] = ra0; *(uint4*)&As[lr][lc * 8 + 8] = ra1;     \
        *(uint4*)&Bs[lr][lc * 8] = rb0; *(uint4*)&Bs[lr][lc * 8 + 8] = rb1;     \
        __syncthreads();                                                        \
    }                                                                           \
    compute();

// ---------------- decoder FINAL (3-term) ----------------
__global__ __launch_bounds__(256, 2)
void mma_final_kernel(const __nv_bfloat16* __restrict__ Ah,
                      const __nv_bfloat16* __restrict__ Al,
                      const __nv_bfloat16* __restrict__ Bh,
                      const __nv_bfloat16* __restrict__ Bl,
                      const float* __restrict__ bias,
                      float* __restrict__ C0, float* __restrict__ C1,
                      int rowSplit, int N)
{
    __shared__ __align__(16) __nv_bfloat16 As[128][40];
    __shared__ __align__(16) __nv_bfloat16 Bs[128][40];
    const int tid = threadIdx.x;
    const int wid = tid >> 5, lane = tid & 31;
    const int wr = wid >> 2, wc = wid & 3;
    const int rowBase = blockIdx.y * 128;
    const int colBase = blockIdx.x * 128;

    MMA_CORE_BODY(24, Ah, Al, Bh, Bl)

#pragma unroll
    for (int mt = 0; mt < 4; mt++) {
        int row0 = rowBase + wr * 64 + mt * 16 + (lane >> 2);
#pragma unroll
        for (int h = 0; h < 2; h++) {
            int row = row0 + h * 8;
            float* cr = (row < rowSplit) ? (C0 + (size_t)row * N)
                                         : (C1 + (size_t)(row - rowSplit) * N);
#pragma unroll
            for (int nt = 0; nt < 4; nt++) {
                int col = colBase + wc * 32 + nt * 8 + (lane & 3) * 2;
                float2 bb = *(const float2*)(bias + col);
                float2 v;
                v.x = acc[mt][nt][h * 2 + 0] + bb.x;
                v.y = acc[mt][nt][h * 2 + 1] + bb.y;
                *(float2*)(cr + col) = v;
            }
        }
    }
}

// ---------------- decoder RES block (3-term; a/b merged over blockIdx.z) ----
struct RArgs {
    const float* Af;
    const __nv_bfloat16 *Ah, *Al, *Bh, *Bl;
    const float* bias;
    float* Cf;
    __nv_bfloat16 *Ch, *Cl;
};

template<bool WF32>
__global__ __launch_bounds__(256, 2)
void mma_res_kernel(RArgs r0, RArgs r1)
{
    const RArgs r = blockIdx.z ? r1 : r0;
    __shared__ __align__(16) __nv_bfloat16 As[128][40];
    __shared__ __align__(16) __nv_bfloat16 Bs[128][40];
    const int tid = threadIdx.x;
    const int wid = tid >> 5, lane = tid & 31;
    const int wr = wid >> 2, wc = wid & 3;
    const int rowBase = blockIdx.y * 128;
    const int colBase = blockIdx.x * 128;

    MMA_CORE_BODY(24, r.Ah, r.Al, r.Bh, r.Bl)

#pragma unroll
    for (int mt = 0; mt < 4; mt++) {
        int row0 = rowBase + wr * 64 + mt * 16 + (lane >> 2);
#pragma unroll
        for (int h = 0; h < 2; h++) {
            int row = row0 + h * 8;
#pragma unroll
            for (int nt = 0; nt < 4; nt++) {
                int col = colBase + wc * 32 + nt * 8 + (lane & 3) * 2;
                size_t off = (size_t)row * 256 + col;
                float2 bb = *(const float2*)(r.bias + col);
                float2 rv = *(const float2*)(r.Af + off);
                float vx = rv.x + fmaxf(acc[mt][nt][h * 2 + 0] + bb.x, 0.f);
                float vy = rv.y + fmaxf(acc[mt][nt][h * 2 + 1] + bb.y, 0.f);
                if (WF32) { float2 o; o.x = vx; o.y = vy; *(float2*)(r.Cf + off) = o; }
                __nv_bfloat162 hh, ll;
                hh.x = __float2bfloat16(vx); hh.y = __float2bfloat16(vy);
                ll.x = __float2bfloat16(vx - __bfloat162float(hh.x));
                ll.y = __float2bfloat16(vy - __bfloat162float(hh.y));
                *(__nv_bfloat162*)(r.Ch + off) = hh;
                *(__nv_bfloat162*)(r.Cl + off) = ll;
            }
        }
    }
}

// ---------------- VQ phase 1: SINGLE-term zh·eh scores (selection only) -----
__global__ __launch_bounds__(256, 2)
void vq_mma_kernel()
{
    __shared__ __align__(16) __nv_bfloat16 As[128][40];
    __shared__ __align__(16) __nv_bfloat16 Bs[128][40];
    const int tid = threadIdx.x;
    const int wid = tid >> 5, lane = tid & 31;
    const int wr = wid >> 2, wc = wid & 3;
    const int rowBase = blockIdx.y * 128;
    const int colBase = blockIdx.x * 128;
    const int bz = blockIdx.z;
    const __nv_bfloat16* Zh = bz ? g_zh_b : g_zh_a;
    short* Q = bz ? g_q_b : g_q_a;
    int* qmax = bz ? g_qmax_b : g_qmax_a;

    MMA_CORE_BODY(8, Zh, Zh, g_eh, g_eh)   // ITERS=8 -> only Ah*Bh term

#pragma unroll
    for (int mt = 0; mt < 4; mt++) {
        int row0 = rowBase + wr * 64 + mt * 16 + (lane >> 2);
#pragma unroll
        for (int h = 0; h < 2; h++) {
            int row = row0 + h * 8;
            int mq = INT_MIN;
#pragma unroll
            for (int nt = 0; nt < 4; nt++) {
                int col = colBase + wc * 32 + nt * 8 + (lane & 3) * 2;
                float t0 = 2.f * acc[mt][nt][h * 2 + 0];
                float t1 = 2.f * acc[mt][nt][h * 2 + 1];
                int q0 = __float2int_rn(t0 * 524288.f);
                int q1 = __float2int_rn(t1 * 524288.f);
                q0 = max(-32000, min(32000, q0));
                q1 = max(-32000, min(32000, q1));
                mq = max(mq, max(q0, q1));
                short2 sv; sv.x = (short)q0; sv.y = (short)q1;
                *(short2*)(Q + (size_t)row * NCODE + col) = sv;
            }
            mq = max(mq, __shfl_xor_sync(0xffffffffu, mq, 1));
            mq = max(mq, __shfl_xor_sync(0xffffffffu, mq, 2));
            if ((lane & 3) == 0) atomicMax(&qmax[row], mq);
        }
    }
}

// ---------------- VQ phase 2 (exact serial fp32 chain — unchanged math) -----
__global__ __launch_bounds__(256)
void vq_select_kernel(const float* __restrict__ Z0, const float* __restrict__ Z1,
                      const float* __restrict__ E)
{
    const int row = blockIdx.x, bz = blockIdx.y;
    const int tid = threadIdx.x;
    const float* Zr = (bz ? Z1 : Z0) + (size_t)row * DLAT;
    const short* Q = (bz ? g_q_b : g_q_a) + (size_t)row * NCODE;
    const int thr = (bz ? g_qmax_b : g_qmax_a)[row] - QTHR;
    const double zz = (bz ? g_zz_b : g_zz_a)[row];

    __shared__ float zs[DLAT];
    __shared__ int cnt;
    __shared__ int cand[128];
    __shared__ unsigned long long best;
    zs[tid] = Zr[tid];
    if (tid == 0) { cnt = 0; best = ~0ull; }
    __syncthreads();

    const short2* Q2 = (const short2*)Q;
#pragma unroll
    for (int it = 0; it < 16; it++) {
        int i2 = tid + it * 256;
        short2 v = Q2[i2];
        if (v.x >= thr) { int p = atomicAdd(&cnt, 1); if (p < 128) cand[p] = i2 * 2; }
        if (v.y >= thr) { int p = atomicAdd(&cnt, 1); if (p < 128) cand[p] = i2 * 2 + 1; }
    }
    __syncthreads();

    int n = min(cnt, 128);
    if (tid < n) {
        int c = cand[tid];
        const float* e = E + (size_t)c * DLAT;
        float accv = 0.f;
#pragma unroll 8
        for (int k = 0; k < DLAT; k++) accv = fmaf(zs[k], e[k], accv);
        double t = 2.0 * (double)accv;
        double d = zz - t;
        long long db = __double_as_longlong(d);
        int ebias = (int)((db >> 52) & 0x7ff);
        double cell = __longlong_as_double((long long)(ebias - 23) << 52);
        double r = cell * rint(t / cell);
        float rf = (float)r;
        unsigned u = __float_as_uint(rf);
        u = (u & 0x80000000u) ? ~u : (u | 0x80000000u);
        unsigned long long key = ((unsigned long long)(~u) << 32) | (unsigned)c;
        atomicMin(&best, key);
    }
    __syncthreads();
    if (tid == 0) (bz ? g_win_b : g_win_a)[row] = (int)(best & 0xffffffffull);
}

// ---------------- VQ finalize ----------------
__global__ void vq_finalize_kernel(const float* __restrict__ Z0, const float* __restrict__ Z1,
                                   const float* __restrict__ E,
                                   float* __restrict__ zq0, float* __restrict__ zq1,
                                   float* __restrict__ ls0, float* __restrict__ ls1)
{
    const int bz = blockIdx.y;
    const float* Z = bz ? Z1 : Z0;
    float* zq = bz ? zq1 : zq0;
    float* loss = bz ? ls1 : ls0;
    int row  = blockIdx.x * 8 + (threadIdx.x >> 5);
    int lane = threadIdx.x & 31;
    int idx  = (bz ? g_win_b : g_win_a)[row];
    const float4* zp = reinterpret_cast<const float4*>(Z) + (size_t)row * (DLAT / 4);
    const float4* ep = reinterpret_cast<const float4*>(E) + (size_t)idx * (DLAT / 4);
    float4* qp = reinterpret_cast<float4*>(zq) + (size_t)row * (DLAT / 4);
    size_t srow = ((size_t)bz * BATCH + row) * DLAT;
    float s = 0.f;
#pragma unroll
    for (int t = 0; t < 2; t++) {
        float4 z = zp[lane + 32 * t], e = ep[lane + 32 * t];
        float dx = e.x - z.x, dy = e.y - z.y, dz = e.z - z.z, dw = e.w - z.w;
        float4 o;
        o.x = z.x + dx; o.y = z.y + dy; o.z = z.z + dz; o.w = z.w + dw;
        qp[lane + 32 * t] = o;
        float vv[4] = {o.x, o.y, o.z, o.w};
#pragma unroll
        for (int p = 0; p < 2; p++) {
            __nv_bfloat162 hh, ll;
            hh.x = __float2bfloat16(vv[p * 2 + 0]);
            hh.y = __float2bfloat16(vv[p * 2 + 1]);
            ll.x = __float2bfloat16(vv[p * 2 + 0] - __bfloat162float(hh.x));
            ll.y = __float2bfloat16(vv[p * 2 + 1] - __bfloat162float(hh.y));
            size_t eo = srow + (lane + 32 * t) * 4 + p * 2;
            *(__nv_bfloat162*)(g_zqh + eo) = hh;
            *(__nv_bfloat162*)(g_zql + eo) = ll;
        }
        s += dx * dx + dy * dy + dz * dz + dw * dw;
    }
#pragma unroll
    for (int o = 16; o; o >>= 1) s += __shfl_down_sync(0xffffffffu, s, o);
    if (lane == 0) loss[row] = s + BETA_F * s;
}

// ---------------- launcher ----------------
extern "C" void kernel_launch(void* const* d_in, const int* in_sizes, int n_in,
                              void* d_out, int out_size)
{
    const float* x_a      = (const float*)d_in[0];
    const float* x_b      = (const float*)d_in[1];
    const float* enc_a_w  = (const float*)d_in[2];
    const float* enc_a_b  = (const float*)d_in[3];
    const float* enc_a_rw = (const float*)d_in[4];
    const float* enc_a_rb = (const float*)d_in[5];
    const float* enc_b_w  = (const float*)d_in[6];
    const float* enc_b_b  = (const float*)d_in[7];
    const float* enc_b_rw = (const float*)d_in[8];
    const float* enc_b_rb = (const float*)d_in[9];
    const float* dec_a_rw = (const float*)d_in[10];
    const float* dec_a_rb = (const float*)d_in[11];
    const float* dec_a_w  = (const float*)d_in[12];
    const float* dec_a_b  = (const float*)d_in[13];
    const float* dec_b_rw = (const float*)d_in[14];
    const float* dec_b_rb = (const float*)d_in[15];
    const float* dec_b_w  = (const float*)d_in[16];
    const float* dec_b_b  = (const float*)d_in[17];
    const float* codebook = (const float*)d_in[18];

    float *ze_a0, *ze_a1, *ze_b0, *ze_b1, *h1a, *h1b;
    double *zz_a, *zz_b;
    __nv_bfloat16 *zh_a, *zl_a, *zh_b, *zl_b, *eh, *el, *zqh, *zql;
    __nv_bfloat16 *s1h_a, *s1l_a, *s0h_a, *s0l_a, *s1h_b, *s1l_b, *s0h_b, *s0l_b;
    __nv_bfloat16 *wth_a, *wtl_a, *wth_b, *wtl_b;
    __nv_bfloat16 *rwth_a, *rwtl_a, *rwth_b, *rwtl_b;
    cudaGetSymbolAddress((void**)&ze_a0, g_ze_a0);
    cudaGetSymbolAddress((void**)&ze_a1, g_ze_a1);
    cudaGetSymbolAddress((void**)&ze_b0, g_ze_b0);
    cudaGetSymbolAddress((void**)&ze_b1, g_ze_b1);
    cudaGetSymbolAddress((void**)&h1a, g_h1a);
    cudaGetSymbolAddress((void**)&h1b, g_h1b);
    cudaGetSymbolAddress((void**)&zz_a, g_zz_a);
    cudaGetSymbolAddress((void**)&zz_b, g_zz_b);
    cudaGetSymbolAddress((void**)&zh_a, g_zh_a);
    cudaGetSymbolAddress((void**)&zl_a, g_zl_a);
    cudaGetSymbolAddress((void**)&zh_b, g_zh_b);
    cudaGetSymbolAddress((void**)&zl_b, g_zl_b);
    cudaGetSymbolAddress((void**)&eh, g_eh);
    cudaGetSymbolAddress((void**)&el, g_el);
    cudaGetSymbolAddress((void**)&zqh, g_zqh);
    cudaGetSymbolAddress((void**)&zql, g_zql);
    cudaGetSymbolAddress((void**)&s1h_a, g_s1h_a);
    cudaGetSymbolAddress((void**)&s1l_a, g_s1l_a);
    cudaGetSymbolAddress((void**)&s0h_a, g_s0h_a);
    cudaGetSymbolAddress((void**)&s0l_a, g_s0l_a);
    cudaGetSymbolAddress((void**)&s1h_b, g_s1h_b);
    cudaGetSymbolAddress((void**)&s1l_b, g_s1l_b);
    cudaGetSymbolAddress((void**)&s0h_b, g_s0h_b);
    cudaGetSymbolAddress((void**)&s0l_b, g_s0l_b);
    cudaGetSymbolAddress((void**)&wth_a, g_wth_a);
    cudaGetSymbolAddress((void**)&wtl_a, g_wtl_a);
    cudaGetSymbolAddress((void**)&wth_b, g_wth_b);
    cudaGetSymbolAddress((void**)&wtl_b, g_wtl_b);
    cudaGetSymbolAddress((void**)&rwth_a, g_rwth_a);
    cudaGetSymbolAddress((void**)&rwtl_a, g_rwtl_a);
    cudaGetSymbolAddress((void**)&rwth_b, g_rwth_b);
    cudaGetSymbolAddress((void**)&rwtl_b, g_rwtl_b);

    float* out = (float*)d_out;
    const size_t OFF_ZA = 0;
    const size_t OFF_ZB = (size_t)BATCH * DLAT;
    const size_t OFF_LA = 2 * OFF_ZB;
    const size_t OFF_LB = OFF_LA + BATCH;
    const size_t OFF_RA = OFF_LB + BATCH;
    const size_t OFF_RB = OFF_RA + (size_t)BATCH * DINA;
    const size_t OFF_XA = OFF_RB + (size_t)BATCH * DINB;
    const size_t OFF_XB = OFF_XA + (size_t)BATCH * DINA;

    init_qmax_kernel<<<(BATCH + 255) / 256, 256>>>();
    wtsplit_kernel<<<DINA, 256>>>(dec_a_w, wth_a, wtl_a, DINA);
    wtsplit_kernel<<<DINB, 256>>>(dec_b_w, wth_b, wtl_b, DINB);
    wtsplit_kernel<<<DLAT, 256>>>(dec_a_rw, rwth_a, rwtl_a, DLAT);
    wtsplit_kernel<<<DLAT, 256>>>(dec_a_rw + DLAT * DLAT, rwth_a + DLAT * DLAT,
                                  rwtl_a + DLAT * DLAT, DLAT);
    wtsplit_kernel<<<DLAT, 256>>>(dec_b_rw, rwth_b, rwtl_b, DLAT);
    wtsplit_kernel<<<DLAT, 256>>>(dec_b_rw + DLAT * DLAT, rwth_b + DLAT * DLAT,
                                  rwtl_b + DLAT * DLAT, DLAT);
    split1_kernel<<<(NCODE * DLAT / 4 + 255) / 256, 256>>>(codebook, eh, el,
                                                           NCODE * DLAT / 4);

    // encoders (exact scalar fp32 chains — argmin-critical, proven)
    gemm_kernel<true, false><<<dim3(2, BATCH / 64, 2), 256>>>(
        GArgs{x_a, enc_a_w, enc_a_b, ze_a0, DINA},
        GArgs{x_b, enc_b_w, enc_b_b, ze_b0, DINB});
    gemm_kernel<true, true><<<dim3(2, BATCH / 64, 2), 256>>>(
        GArgs{ze_a0, enc_a_rw, enc_a_rb, ze_a1, DLAT},
        GArgs{ze_b0, enc_b_rw, enc_b_rb, ze_b1, DLAT});
    gemm_kernel<true, true><<<dim3(2, BATCH / 64, 2), 256>>>(
        GArgs{ze_a1, enc_a_rw + DLAT * DLAT, enc_a_rb + DLAT, ze_a0, DLAT},
        GArgs{ze_b1, enc_b_rw + DLAT * DLAT, enc_b_rb + DLAT, ze_b0, DLAT});

    zz_kernel<<<dim3(BATCH / 8, 2), 256>>>(ze_a0, ze_b0, zz_a, zz_b);
    split1_kernel<<<(BATCH * DLAT / 4 + 255) / 256, 256>>>(ze_a0, zh_a, zl_a,
                                                           BATCH * DLAT / 4);
    split1_kernel<<<(BATCH * DLAT / 4 + 255) / 256, 256>>>(ze_b0, zh_b, zl_b,
                                                           BATCH * DLAT / 4);

    // VQ: single-term approx scores (selection only), then exact resolve
    vq_mma_kernel<<<dim3(NCODE / 128, BATCH / 128, 2), 256>>>();
    vq_select_kernel<<<dim3(BATCH, 2), 256>>>(ze_a0, ze_b0, codebook);

    vq_finalize_kernel<<<dim3(BATCH / 8, 2), 256>>>(
        ze_a0, ze_b0, codebook,
        out + OFF_ZA, out + OFF_ZB, out + OFF_LA, out + OFF_LB);

    const float* Zq = out;

    // decoder res blocks (a+b merged per layer)
    mma_res_kernel<true><<<dim3(2, 2 * BATCH / 128, 2), 256>>>(
        RArgs{Zq, zqh, zql, rwth_a, rwtl_a, dec_a_rb, h1a, s1h_a, s1l_a},
        RArgs{Zq, zqh, zql, rwth_b, rwtl_b, dec_b_rb, h1b, s1h_b, s1l_b});
    mma_res_kernel<false><<<dim3(2, 2 * BATCH / 128, 2), 256>>>(
        RArgs{h1a, s1h_a, s1l_a, rwth_a + DLAT * DLAT, rwtl_a + DLAT * DLAT,
              dec_a_rb + DLAT, nullptr, s0h_a, s0l_a},
        RArgs{h1b, s1h_b, s1l_b, rwth_b + DLAT * DLAT, rwtl_b + DLAT * DLAT,
              dec_b_rb + DLAT, nullptr, s0h_b, s0l_b});

    mma_final_kernel<<<dim3(DINA / 128, 2 * BATCH / 128), 256>>>(
        s0h_a, s0l_a, wth_a, wtl_a, dec_a_b,
        out + OFF_RA, out + OFF_XA, BATCH, DINA);
    mma_final_kernel<<<dim3(DINB / 128, 2 * BATCH / 128), 256>>>(
        s0h_b, s0l_b, wth_b, wtl_b, dec_b_b,
        out + OFF_XB, out + OFF_RB, BATCH, DINB);
}

// round 16
// speedup vs baseline: 1.2596x; 1.0005x over previous
#include <cuda_runtime.h>
#include <cuda_bf16.h>
#include <cstdint>
#include <climits>

#define BATCH   8192
#define DINA    4096
#define DINB    2048
#define DLAT    256
#define NCODE   8192
#define BETA_F  0.25f
#define QTHR    160      // select margin in int16 cells (3e-4 in t)

// ---------------- scratch (static __device__ — no allocation) ----------------
__device__ float g_ze_a0[BATCH * DLAT];
__device__ float g_ze_a1[BATCH * DLAT];
__device__ float g_ze_b0[BATCH * DLAT];
__device__ float g_ze_b1[BATCH * DLAT];
__device__ float g_h1a[2 * BATCH * DLAT];
__device__ float g_h1b[2 * BATCH * DLAT];
__device__ double g_zz_a[BATCH];
__device__ double g_zz_b[BATCH];
__device__ int g_qmax_a[BATCH];
__device__ int g_qmax_b[BATCH];
__device__ int g_win_a[BATCH];
__device__ int g_win_b[BATCH];
__device__ short g_q_a[(size_t)BATCH * NCODE];
__device__ short g_q_b[(size_t)BATCH * NCODE];
// bf16 operands
__device__ __nv_bfloat16 g_zh_a[BATCH * DLAT];      // z hi (epilogue-fused)
__device__ __nv_bfloat16 g_zh_b[BATCH * DLAT];
__device__ __nv_bfloat16 g_eh[NCODE * DLAT];
__device__ __nv_bfloat16 g_el[NCODE * DLAT];
__device__ __nv_bfloat16 g_zqh[2 * BATCH * DLAT];
__device__ __nv_bfloat16 g_zql[2 * BATCH * DLAT];
__device__ __nv_bfloat16 g_s1h_a[2 * BATCH * DLAT];
__device__ __nv_bfloat16 g_s1l_a[2 * BATCH * DLAT];
__device__ __nv_bfloat16 g_s0h_a[2 * BATCH * DLAT];
__device__ __nv_bfloat16 g_s0l_a[2 * BATCH * DLAT];
__device__ __nv_bfloat16 g_s1h_b[2 * BATCH * DLAT];
__device__ __nv_bfloat16 g_s1l_b[2 * BATCH * DLAT];
__device__ __nv_bfloat16 g_s0h_b[2 * BATCH * DLAT];
__device__ __nv_bfloat16 g_s0l_b[2 * BATCH * DLAT];
__device__ __nv_bfloat16 g_wth_a[DINA * DLAT];
__device__ __nv_bfloat16 g_wtl_a[DINA * DLAT];
__device__ __nv_bfloat16 g_wth_b[DINB * DLAT];
__device__ __nv_bfloat16 g_wtl_b[DINB * DLAT];
__device__ __nv_bfloat16 g_rwth_a[2 * DLAT * DLAT];
__device__ __nv_bfloat16 g_rwtl_a[2 * DLAT * DLAT];
__device__ __nv_bfloat16 g_rwth_b[2 * DLAT * DLAT];
__device__ __nv_bfloat16 g_rwtl_b[2 * DLAT * DLAT];

__device__ __forceinline__ uint32_t smem_u32(const void* p) {
    uint32_t a;
    asm("{ .reg .u64 t; cvta.to.shared.u64 t, %1; cvt.u32.u64 %0, t; }"
        : "=r"(a) : "l"(p));
    return a;
}
__device__ __forceinline__ void cp16(uint32_t s, const void* g) {
    asm volatile("cp.async.cg.shared.global [%0], [%1], 16;" :: "r"(s), "l"(g));
}

// ---------------- small helpers ----------------
__global__ void init_qmax_kernel() {
    int i = blockIdx.x * blockDim.x + threadIdx.x;
    if (i < BATCH) { g_qmax_a[i] = INT_MIN; g_qmax_b[i] = INT_MIN; }
}

__global__ void zz_kernel(const float* __restrict__ Z0, const float* __restrict__ Z1,
                          double* __restrict__ zz0, double* __restrict__ zz1) {
    const float* Z = blockIdx.y ? Z1 : Z0;
    double* zz = blockIdx.y ? zz1 : zz0;
    int row  = blockIdx.x * 8 + (threadIdx.x >> 5);
    int lane = threadIdx.x & 31;
    const float4* zp = reinterpret_cast<const float4*>(Z) + (size_t)row * (DLAT / 4);
    double s = 0.0;
#pragma unroll
    for (int t = 0; t < 2; t++) {
        float4 v = zp[lane + 32 * t];
        s += (double)v.x * v.x + (double)v.y * v.y
           + (double)v.z * v.z + (double)v.w * v.w;
    }
#pragma unroll
    for (int o = 16; o; o >>= 1) s += __shfl_down_sync(0xffffffffu, s, o);
    if (lane == 0) zz[row] = s;
}

__global__ void split1_kernel(const float* __restrict__ x,
                              __nv_bfloat16* __restrict__ hi,
                              __nv_bfloat16* __restrict__ lo, int n4)
{
    int i = blockIdx.x * blockDim.x + threadIdx.x;
    if (i >= n4) return;
    float4 v = ((const float4*)x)[i];
    __nv_bfloat16 hx = __float2bfloat16(v.x), hy = __float2bfloat16(v.y);
    __nv_bfloat16 hz = __float2bfloat16(v.z), hw = __float2bfloat16(v.w);
    __nv_bfloat162 h01; h01.x = hx; h01.y = hy;
    __nv_bfloat162 h23; h23.x = hz; h23.y = hw;
    __nv_bfloat162 l01, l23;
    l01.x = __float2bfloat16(v.x - __bfloat162float(hx));
    l01.y = __float2bfloat16(v.y - __bfloat162float(hy));
    l23.x = __float2bfloat16(v.z - __bfloat162float(hz));
    l23.y = __float2bfloat16(v.w - __bfloat162float(hw));
    ((__nv_bfloat162*)hi)[i * 2 + 0] = h01;
    ((__nv_bfloat162*)hi)[i * 2 + 1] = h23;
    ((__nv_bfloat162*)lo)[i * 2 + 0] = l01;
    ((__nv_bfloat162*)lo)[i * 2 + 1] = l23;
}

__global__ void wtsplit_kernel(const float* __restrict__ W,
                               __nv_bfloat16* __restrict__ th,
                               __nv_bfloat16* __restrict__ tl, int N)
{
    int i = blockIdx.x * blockDim.x + threadIdx.x;
    int n = i >> 8, k = i & 255;
    float x = W[(size_t)k * N + n];
    __nv_bfloat16 h = __float2bfloat16(x);
    th[i] = h;
    tl[i] = __float2bfloat16(x - __bfloat162float(h));
}

// ---------------- SIMT fused GEMM (exact scalar fp32 chains — encoders) -----
// WZH: additionally write bf16-hi of the output (fused z split for VQ).
struct GArgs { const float* A; const float* W; const float* bias; float* C;
               __nv_bfloat16* zh; int K; };

template<bool RELU, bool RESID, bool WZH>
__global__ __launch_bounds__(256, 3)
void gemm_kernel(GArgs g0, GArgs g1)
{
    const GArgs g = blockIdx.z ? g1 : g0;
    const int K = g.K;
    __shared__ float As[2][8][68];
    __shared__ float Bs[2][8][128];
    const int tid = threadIdx.x;
    const int tx = tid & 15, ty = tid >> 4;
    const int rowBase = blockIdx.y * 64;
    const int colBase = blockIdx.x * 128;

    const int ar = tid >> 1, ac4 = (tid & 1) * 4;
    const bool aAct = tid < 128;
    const float* Ap = aAct ? (g.A + (size_t)(rowBase + ar) * K + ac4) : g.A;
    const int br = tid >> 5, bc = (tid & 31) * 4;
    const float* Wp = g.W + (size_t)br * 256 + colBase + bc;
    const uint32_t bs0 = smem_u32(&Bs[0][br][bc]);
    const uint32_t bs1 = smem_u32(&Bs[1][br][bc]);

    float acc[4][8];
#pragma unroll
    for (int i = 0; i < 4; i++)
#pragma unroll
        for (int j = 0; j < 8; j++) acc[i][j] = 0.f;

    float4 av = make_float4(0.f, 0.f, 0.f, 0.f);
    if (aAct) av = *(const float4*)Ap;
    cp16(bs0, Wp);
    asm volatile("cp.async.commit_group;");
    if (aAct) {
        As[0][ac4 + 0][ar] = av.x; As[0][ac4 + 1][ar] = av.y;
        As[0][ac4 + 2][ar] = av.z; As[0][ac4 + 3][ar] = av.w;
    }
    asm volatile("cp.async.wait_group 0;");
    __syncthreads();

    const int nIter = K >> 3;
    int buf = 0;
#pragma unroll 1
    for (int i = 0; i < nIter; i++) {
        const bool more = (i + 1 < nIter);
        if (more) {
            if (aAct) av = *(const float4*)(Ap + (size_t)(i + 1) * 8);
            cp16(buf ? bs0 : bs1, Wp + (size_t)(i + 1) * 8 * 256);
            asm volatile("cp.async.commit_group;");
        }
#pragma unroll
        for (int kk = 0; kk < 8; kk++) {
            float4 a4 = *(const float4*)&As[buf][kk][ty * 4];
            float4 b0 = *(const float4*)&Bs[buf][kk][tx * 4];
            float4 b1 = *(const float4*)&Bs[buf][kk][tx * 4 + 64];
            float a[4] = {a4.x, a4.y, a4.z, a4.w};
            float b[8] = {b0.x, b0.y, b0.z, b0.w, b1.x, b1.y, b1.z, b1.w};
#pragma unroll
            for (int i2 = 0; i2 < 4; i2++)
#pragma unroll
                for (int j = 0; j < 8; j++)
                    acc[i2][j] = fmaf(a[i2], b[j], acc[i2][j]);
        }
        if (more) {
            if (aAct) {
                int nb = buf ^ 1;
                As[nb][ac4 + 0][ar] = av.x; As[nb][ac4 + 1][ar] = av.y;
                As[nb][ac4 + 2][ar] = av.z; As[nb][ac4 + 3][ar] = av.w;
            }
            asm volatile("cp.async.wait_group 0;");
        }
        __syncthreads();
        buf ^= 1;
    }

#pragma unroll
    for (int i2 = 0; i2 < 4; i2++) {
        int row = rowBase + ty * 4 + i2;
        float* cr = g.C + (size_t)row * 256;
        const float* rr = RESID ? (g.A + (size_t)row * 256) : nullptr;
#pragma unroll
        for (int gg = 0; gg < 2; gg++) {
            int col = colBase + tx * 4 + gg * 64;
            float4 bb = *(const float4*)(g.bias + col);
            float4 v;
            v.x = acc[i2][gg * 4 + 0] + bb.x;
            v.y = acc[i2][gg * 4 + 1] + bb.y;
            v.z = acc[i2][gg * 4 + 2] + bb.z;
            v.w = acc[i2][gg * 4 + 3] + bb.w;
            if (RELU) {
                v.x = fmaxf(v.x, 0.f); v.y = fmaxf(v.y, 0.f);
                v.z = fmaxf(v.z, 0.f); v.w = fmaxf(v.w, 0.f);
            }
            if (RESID) {
                float4 rv = *(const float4*)(rr + col);
                v.x += rv.x; v.y += rv.y; v.z += rv.z; v.w += rv.w;
            }
            *(float4*)(cr + col) = v;
            if (WZH) {
                __nv_bfloat162 h01, h23;
                h01.x = __float2bfloat16(v.x); h01.y = __float2bfloat16(v.y);
                h23.x = __float2bfloat16(v.z); h23.y = __float2bfloat16(v.w);
                __nv_bfloat162* zp =
                    (__nv_bfloat162*)(g.zh + (size_t)row * 256 + col);
                zp[0] = h01; zp[1] = h23;
            }
        }
    }
}

// =================== bf16 mma core (term-major, proven; ITERS param) ========
#define MMA_CORE_BODY(ITERS, AhP, AlP, BhP, BlP)                                \
    const int lr = tid >> 1;                                                    \
    const int lc = (tid & 1) * 2;                                               \
    const __nv_bfloat16* Asrc[3] = {AhP, AhP, AlP};                             \
    const __nv_bfloat16* Bsrc[3] = {BhP, BlP, BhP};                             \
    float acc[4][4][4];                                                         \
    _Pragma("unroll")                                                           \
    for (int m = 0; m < 4; m++)                                                 \
        _Pragma("unroll")                                                       \
        for (int n = 0; n < 4; n++)                                             \
            _Pragma("unroll")                                                   \
            for (int c = 0; c < 4; c++) acc[m][n][c] = 0.f;                     \
    const uint32_t aAddr = smem_u32(&As[wr * 64 + (lane & 15)][(lane >> 4) * 8]); \
    const uint32_t bAddr = smem_u32(                                            \
        &Bs[wc * 32 + (lane & 7) + ((lane >> 4) & 1) * 8][((lane >> 3) & 1) * 8]); \
    uint4 ra0, ra1, rb0, rb1;                                                   \
    {                                                                           \
        const uint4* ga = (const uint4*)(Asrc[0] + (size_t)(rowBase + lr) * 256); \
        ra0 = ga[lc]; ra1 = ga[lc + 1];                                         \
        const uint4* gb = (const uint4*)(Bsrc[0] + (size_t)(colBase + lr) * 256); \
        rb0 = gb[lc]; rb1 = gb[lc + 1];                                         \
    }                                                                           \
    *(uint4*)&As[lr][lc * 8] = ra0; *(uint4*)&As[lr][lc * 8 + 8] = ra1;         \
    *(uint4*)&Bs[lr][lc * 8] = rb0; *(uint4*)&Bs[lr][lc * 8 + 8] = rb1;         \
    __syncthreads();                                                            \
    auto compute = [&]() {                                                      \
        _Pragma("unroll")                                                       \
        for (int ss = 0; ss < 2; ss++) {                                        \
            uint32_t af[4][4];                                                  \
            _Pragma("unroll")                                                   \
            for (int mt = 0; mt < 4; mt++) {                                    \
                uint32_t addr = aAddr + mt * 16 * 80 + ss * 32;                 \
                asm volatile(                                                   \
                    "ldmatrix.sync.aligned.m8n8.x4.shared.b16 {%0,%1,%2,%3}, [%4];" \
                    : "=r"(af[mt][0]), "=r"(af[mt][1]),                         \
                      "=r"(af[mt][2]), "=r"(af[mt][3]) : "r"(addr));            \
            }                                                                   \
            uint32_t bfr[2][4];                                                 \
            _Pragma("unroll")                                                   \
            for (int bp = 0; bp < 2; bp++) {                                    \
                uint32_t addr = bAddr + bp * 16 * 80 + ss * 32;                 \
                asm volatile(                                                   \
                    "ldmatrix.sync.aligned.m8n8.x4.shared.b16 {%0,%1,%2,%3}, [%4];" \
                    : "=r"(bfr[bp][0]), "=r"(bfr[bp][1]),                       \
                      "=r"(bfr[bp][2]), "=r"(bfr[bp][3]) : "r"(addr));          \
            }                                                                   \
            _Pragma("unroll")                                                   \
            for (int mt = 0; mt < 4; mt++)                                      \
                _Pragma("unroll")                                               \
                for (int nt = 0; nt < 4; nt++) {                                \
                    uint32_t b0 = bfr[nt >> 1][(nt & 1) * 2 + 0];               \
                    uint32_t b1 = bfr[nt >> 1][(nt & 1) * 2 + 1];               \
                    asm volatile(                                               \
                        "mma.sync.aligned.m16n8k16.row.col.f32.bf16.bf16.f32 "  \
                        "{%0,%1,%2,%3}, {%4,%5,%6,%7}, {%8,%9}, {%0,%1,%2,%3};" \
                        : "+f"(acc[mt][nt][0]), "+f"(acc[mt][nt][1]),           \
                          "+f"(acc[mt][nt][2]), "+f"(acc[mt][nt][3])            \
                        : "r"(af[mt][0]), "r"(af[mt][1]),                       \
                          "r"(af[mt][2]), "r"(af[mt][3]), "r"(b0), "r"(b1));    \
                }                                                               \
        }                                                                       \
    };                                                                          \
    for (int iter = 1; iter < (ITERS); iter++) {                                \
        const int t = iter >> 3, k0 = (iter & 7) << 5;                          \
        const uint4* ga = (const uint4*)(Asrc[t] + (size_t)(rowBase + lr) * 256 + k0); \
        ra0 = ga[lc]; ra1 = ga[lc + 1];                                         \
        const uint4* gb = (const uint4*)(Bsrc[t] + (size_t)(colBase + lr) * 256 + k0); \
        rb0 = gb[lc]; rb1 = gb[lc + 1];                                         \
        compute();                                                              \
        __syncthreads();                                                        \
        *(uint4*)&As[lr][lc * 8] = ra0; *(uint4*)&As[lr][lc * 8 + 8] = ra1;     \
        *(uint4*)&Bs[lr][lc * 8] = rb0; *(uint4*)&Bs[lr][lc * 8 + 8] = rb1;     \
        __syncthreads();                                                        \
    }                                                                           \
    compute();

// ---------------- decoder FINAL (3-term; a/b merged, early-exit) ------------
struct FArgs {
    const __nv_bfloat16 *Ah, *Al, *Bh, *Bl;
    const float* bias;
    float *C0, *C1;
    int rowSplit, N, nx;
};

__global__ __launch_bounds__(256, 2)
void mma_final_kernel(FArgs f0, FArgs f1)
{
    const FArgs f = blockIdx.z ? f1 : f0;
    if ((int)blockIdx.x >= f.nx) return;
    __shared__ __align__(16) __nv_bfloat16 As[128][40];
    __shared__ __align__(16) __nv_bfloat16 Bs[128][40];
    const int tid = threadIdx.x;
    const int wid = tid >> 5, lane = tid & 31;
    const int wr = wid >> 2, wc = wid & 3;
    const int rowBase = blockIdx.y * 128;
    const int colBase = blockIdx.x * 128;

    MMA_CORE_BODY(24, f.Ah, f.Al, f.Bh, f.Bl)

#pragma unroll
    for (int mt = 0; mt < 4; mt++) {
        int row0 = rowBase + wr * 64 + mt * 16 + (lane >> 2);
#pragma unroll
        for (int h = 0; h < 2; h++) {
            int row = row0 + h * 8;
            float* cr = (row < f.rowSplit) ? (f.C0 + (size_t)row * f.N)
                                           : (f.C1 + (size_t)(row - f.rowSplit) * f.N);
#pragma unroll
            for (int nt = 0; nt < 4; nt++) {
                int col = colBase + wc * 32 + nt * 8 + (lane & 3) * 2;
                float2 bb = *(const float2*)(f.bias + col);
                float2 v;
                v.x = acc[mt][nt][h * 2 + 0] + bb.x;
                v.y = acc[mt][nt][h * 2 + 1] + bb.y;
                *(float2*)(cr + col) = v;
            }
        }
    }
}

// ---------------- decoder RES block (3-term; a/b merged) --------------------
struct RArgs {
    const float* Af;
    const __nv_bfloat16 *Ah, *Al, *Bh, *Bl;
    const float* bias;
    float* Cf;
    __nv_bfloat16 *Ch, *Cl;
};

template<bool WF32>
__global__ __launch_bounds__(256, 2)
void mma_res_kernel(RArgs r0, RArgs r1)
{
    const RArgs r = blockIdx.z ? r1 : r0;
    __shared__ __align__(16) __nv_bfloat16 As[128][40];
    __shared__ __align__(16) __nv_bfloat16 Bs[128][40];
    const int tid = threadIdx.x;
    const int wid = tid >> 5, lane = tid & 31;
    const int wr = wid >> 2, wc = wid & 3;
    const int rowBase = blockIdx.y * 128;
    const int colBase = blockIdx.x * 128;

    MMA_CORE_BODY(24, r.Ah, r.Al, r.Bh, r.Bl)

#pragma unroll
    for (int mt = 0; mt < 4; mt++) {
        int row0 = rowBase + wr * 64 + mt * 16 + (lane >> 2);
#pragma unroll
        for (int h = 0; h < 2; h++) {
            int row = row0 + h * 8;
#pragma unroll
            for (int nt = 0; nt < 4; nt++) {
                int col = colBase + wc * 32 + nt * 8 + (lane & 3) * 2;
                size_t off = (size_t)row * 256 + col;
                float2 bb = *(const float2*)(r.bias + col);
                float2 rv = *(const float2*)(r.Af + off);
                float vx = rv.x + fmaxf(acc[mt][nt][h * 2 + 0] + bb.x, 0.f);
                float vy = rv.y + fmaxf(acc[mt][nt][h * 2 + 1] + bb.y, 0.f);
                if (WF32) { float2 o; o.x = vx; o.y = vy; *(float2*)(r.Cf + off) = o; }
                __nv_bfloat162 hh, ll;
                hh.x = __float2bfloat16(vx); hh.y = __float2bfloat16(vy);
                ll.x = __float2bfloat16(vx - __bfloat162float(hh.x));
                ll.y = __float2bfloat16(vy - __bfloat162float(hh.y));
                *(__nv_bfloat162*)(r.Ch + off) = hh;
                *(__nv_bfloat162*)(r.Cl + off) = ll;
            }
        }
    }
}

// ---------------- VQ phase 1: single-term zh·eh scores ----------------------
__global__ __launch_bounds__(256, 2)
void vq_mma_kernel()
{
    __shared__ __align__(16) __nv_bfloat16 As[128][40];
    __shared__ __align__(16) __nv_bfloat16 Bs[128][40];
    const int tid = threadIdx.x;
    const int wid = tid >> 5, lane = tid & 31;
    const int wr = wid >> 2, wc = wid & 3;
    const int rowBase = blockIdx.y * 128;
    const int colBase = blockIdx.x * 128;
    const int bz = blockIdx.z;
    const __nv_bfloat16* Zh = bz ? g_zh_b : g_zh_a;
    short* Q = bz ? g_q_b : g_q_a;
    int* qmax = bz ? g_qmax_b : g_qmax_a;

    MMA_CORE_BODY(8, Zh, Zh, g_eh, g_eh)   // ITERS=8 -> only Ah*Bh term

#pragma unroll
    for (int mt = 0; mt < 4; mt++) {
        int row0 = rowBase + wr * 64 + mt * 16 + (lane >> 2);
#pragma unroll
        for (int h = 0; h < 2; h++) {
            int row = row0 + h * 8;
            int mq = INT_MIN;
#pragma unroll
            for (int nt = 0; nt < 4; nt++) {
                int col = colBase + wc * 32 + nt * 8 + (lane & 3) * 2;
                float t0 = 2.f * acc[mt][nt][h * 2 + 0];
                float t1 = 2.f * acc[mt][nt][h * 2 + 1];
                int q0 = __float2int_rn(t0 * 524288.f);
                int q1 = __float2int_rn(t1 * 524288.f);
                q0 = max(-32000, min(32000, q0));
                q1 = max(-32000, min(32000, q1));
                mq = max(mq, max(q0, q1));
                short2 sv; sv.x = (short)q0; sv.y = (short)q1;
                *(short2*)(Q + (size_t)row * NCODE + col) = sv;
            }
            mq = max(mq, __shfl_xor_sync(0xffffffffu, mq, 1));
            mq = max(mq, __shfl_xor_sync(0xffffffffu, mq, 2));
            if ((lane & 3) == 0) atomicMax(&qmax[row], mq);
        }
    }
}

// ---------------- VQ phase 2 (exact serial fp32 chain) ----------------------
__global__ __launch_bounds__(256)
void vq_select_kernel(const float* __restrict__ Z0, const float* __restrict__ Z1,
                      const float* __restrict__ E)
{
    const int row = blockIdx.x, bz = blockIdx.y;
    const int tid = threadIdx.x;
    const float* Zr = (bz ? Z1 : Z0) + (size_t)row * DLAT;
    const short* Q = (bz ? g_q_b : g_q_a) + (size_t)row * NCODE;
    const int thr = (bz ? g_qmax_b : g_qmax_a)[row] - QTHR;
    const double zz = (bz ? g_zz_b : g_zz_a)[row];

    __shared__ float zs[DLAT];
    __shared__ int cnt;
    __shared__ int cand[128];
    __shared__ unsigned long long best;
    zs[tid] = Zr[tid];
    if (tid == 0) { cnt = 0; best = ~0ull; }
    __syncthreads();

    const short2* Q2 = (const short2*)Q;
#pragma unroll
    for (int it = 0; it < 16; it++) {
        int i2 = tid + it * 256;
        short2 v = Q2[i2];
        if (v.x >= thr) { int p = atomicAdd(&cnt, 1); if (p < 128) cand[p] = i2 * 2; }
        if (v.y >= thr) { int p = atomicAdd(&cnt, 1); if (p < 128) cand[p] = i2 * 2 + 1; }
    }
    __syncthreads();

    int n = min(cnt, 128);
    if (tid < n) {
        int c = cand[tid];
        const float* e = E + (size_t)c * DLAT;
        float accv = 0.f;
#pragma unroll 8
        for (int k = 0; k < DLAT; k++) accv = fmaf(zs[k], e[k], accv);
        double t = 2.0 * (double)accv;
        double d = zz - t;
        long long db = __double_as_longlong(d);
        int ebias = (int)((db >> 52) & 0x7ff);
        double cell = __longlong_as_double((long long)(ebias - 23) << 52);
        double r = cell * rint(t / cell);
        float rf = (float)r;
        unsigned u = __float_as_uint(rf);
        u = (u & 0x80000000u) ? ~u : (u | 0x80000000u);
        unsigned long long key = ((unsigned long long)(~u) << 32) | (unsigned)c;
        atomicMin(&best, key);
    }
    __syncthreads();
    if (tid == 0) (bz ? g_win_b : g_win_a)[row] = (int)(best & 0xffffffffull);
}

// ---------------- VQ finalize ----------------
__global__ void vq_finalize_kernel(const float* __restrict__ Z0, const float* __restrict__ Z1,
                                   const float* __restrict__ E,
                                   float* __restrict__ zq0, float* __restrict__ zq1,
                                   float* __restrict__ ls0, float* __restrict__ ls1)
{
    const int bz = blockIdx.y;
    const float* Z = bz ? Z1 : Z0;
    float* zq = bz ? zq1 : zq0;
    float* loss = bz ? ls1 : ls0;
    int row  = blockIdx.x * 8 + (threadIdx.x >> 5);
    int lane = threadIdx.x & 31;
    int idx  = (bz ? g_win_b : g_win_a)[row];
    const float4* zp = reinterpret_cast<const float4*>(Z) + (size_t)row * (DLAT / 4);
    const float4* ep = reinterpret_cast<const float4*>(E) + (size_t)idx * (DLAT / 4);
    float4* qp = reinterpret_cast<float4*>(zq) + (size_t)row * (DLAT / 4);
    size_t srow = ((size_t)bz * BATCH + row) * DLAT;
    float s = 0.f;
#pragma unroll
    for (int t = 0; t < 2; t++) {
        float4 z = zp[lane + 32 * t], e = ep[lane + 32 * t];
        float dx = e.x - z.x, dy = e.y - z.y, dz = e.z - z.z, dw = e.w - z.w;
        float4 o;
        o.x = z.x + dx; o.y = z.y + dy; o.z = z.z + dz; o.w = z.w + dw;
        qp[lane + 32 * t] = o;
        float vv[4] = {o.x, o.y, o.z, o.w};
#pragma unroll
        for (int p = 0; p < 2; p++) {
            __nv_bfloat162 hh, ll;
            hh.x = __float2bfloat16(vv[p * 2 + 0]);
            hh.y = __float2bfloat16(vv[p * 2 + 1]);
            ll.x = __float2bfloat16(vv[p * 2 + 0] - __bfloat162float(hh.x));
            ll.y = __float2bfloat16(vv[p * 2 + 1] - __bfloat162float(hh.y));
            size_t eo = srow + (lane + 32 * t) * 4 + p * 2;
            *(__nv_bfloat162*)(g_zqh + eo) = hh;
            *(__nv_bfloat162*)(g_zql + eo) = ll;
        }
        s += dx * dx + dy * dy + dz * dz + dw * dw;
    }
#pragma unroll
    for (int o = 16; o; o >>= 1) s += __shfl_down_sync(0xffffffffu, s, o);
    if (lane == 0) loss[row] = s + BETA_F * s;
}

// ---------------- launcher ----------------
extern "C" void kernel_launch(void* const* d_in, const int* in_sizes, int n_in,
                              void* d_out, int out_size)
{
    const float* x_a      = (const float*)d_in[0];
    const float* x_b      = (const float*)d_in[1];
    const float* enc_a_w  = (const float*)d_in[2];
    const float* enc_a_b  = (const float*)d_in[3];
    const float* enc_a_rw = (const float*)d_in[4];
    const float* enc_a_rb = (const float*)d_in[5];
    const float* enc_b_w  = (const float*)d_in[6];
    const float* enc_b_b  = (const float*)d_in[7];
    const float* enc_b_rw = (const float*)d_in[8];
    const float* enc_b_rb = (const float*)d_in[9];
    const float* dec_a_rw = (const float*)d_in[10];
    const float* dec_a_rb = (const float*)d_in[11];
    const float* dec_a_w  = (const float*)d_in[12];
    const float* dec_a_b  = (const float*)d_in[13];
    const float* dec_b_rw = (const float*)d_in[14];
    const float* dec_b_rb = (const float*)d_in[15];
    const float* dec_b_w  = (const float*)d_in[16];
    const float* dec_b_b  = (const float*)d_in[17];
    const float* codebook = (const float*)d_in[18];

    float *ze_a0, *ze_a1, *ze_b0, *ze_b1, *h1a, *h1b;
    double *zz_a, *zz_b;
    __nv_bfloat16 *zh_a, *zh_b, *eh, *el, *zqh, *zql;
    __nv_bfloat16 *s1h_a, *s1l_a, *s0h_a, *s0l_a, *s1h_b, *s1l_b, *s0h_b, *s0l_b;
    __nv_bfloat16 *wth_a, *wtl_a, *wth_b, *wtl_b;
    __nv_bfloat16 *rwth_a, *rwtl_a, *rwth_b, *rwtl_b;
    cudaGetSymbolAddress((void**)&ze_a0, g_ze_a0);
    cudaGetSymbolAddress((void**)&ze_a1, g_ze_a1);
    cudaGetSymbolAddress((void**)&ze_b0, g_ze_b0);
    cudaGetSymbolAddress((void**)&ze_b1, g_ze_b1);
    cudaGetSymbolAddress((void**)&h1a, g_h1a);
    cudaGetSymbolAddress((void**)&h1b, g_h1b);
    cudaGetSymbolAddress((void**)&zz_a, g_zz_a);
    cudaGetSymbolAddress((void**)&zz_b, g_zz_b);
    cudaGetSymbolAddress((void**)&zh_a, g_zh_a);
    cudaGetSymbolAddress((void**)&zh_b, g_zh_b);
    cudaGetSymbolAddress((void**)&eh, g_eh);
    cudaGetSymbolAddress((void**)&el, g_el);
    cudaGetSymbolAddress((void**)&zqh, g_zqh);
    cudaGetSymbolAddress((void**)&zql, g_zql);
    cudaGetSymbolAddress((void**)&s1h_a, g_s1h_a);
    cudaGetSymbolAddress((void**)&s1l_a, g_s1l_a);
    cudaGetSymbolAddress((void**)&s0h_a, g_s0h_a);
    cudaGetSymbolAddress((void**)&s0l_a, g_s0l_a);
    cudaGetSymbolAddress((void**)&s1h_b, g_s1h_b);
    cudaGetSymbolAddress((void**)&s1l_b, g_s1l_b);
    cudaGetSymbolAddress((void**)&s0h_b, g_s0h_b);
    cudaGetSymbolAddress((void**)&s0l_b, g_s0l_b);
    cudaGetSymbolAddress((void**)&wth_a, g_wth_a);
    cudaGetSymbolAddress((void**)&wtl_a, g_wtl_a);
    cudaGetSymbolAddress((void**)&wth_b, g_wth_b);
    cudaGetSymbolAddress((void**)&wtl_b, g_wtl_b);
    cudaGetSymbolAddress((void**)&rwth_a, g_rwth_a);
    cudaGetSymbolAddress((void**)&rwtl_a, g_rwtl_a);
    cudaGetSymbolAddress((void**)&rwth_b, g_rwth_b);
    cudaGetSymbolAddress((void**)&rwtl_b, g_rwtl_b);

    float* out = (float*)d_out;
    const size_t OFF_ZA = 0;
    const size_t OFF_ZB = (size_t)BATCH * DLAT;
    const size_t OFF_LA = 2 * OFF_ZB;
    const size_t OFF_LB = OFF_LA + BATCH;
    const size_t OFF_RA = OFF_LB + BATCH;
    const size_t OFF_RB = OFF_RA + (size_t)BATCH * DINA;
    const size_t OFF_XA = OFF_RB + (size_t)BATCH * DINB;
    const size_t OFF_XB = OFF_XA + (size_t)BATCH * DINA;

    init_qmax_kernel<<<(BATCH + 255) / 256, 256>>>();
    wtsplit_kernel<<<DINA, 256>>>(dec_a_w, wth_a, wtl_a, DINA);
    wtsplit_kernel<<<DINB, 256>>>(dec_b_w, wth_b, wtl_b, DINB);
    wtsplit_kernel<<<DLAT, 256>>>(dec_a_rw, rwth_a, rwtl_a, DLAT);
    wtsplit_kernel<<<DLAT, 256>>>(dec_a_rw + DLAT * DLAT, rwth_a + DLAT * DLAT,
                                  rwtl_a + DLAT * DLAT, DLAT);
    wtsplit_kernel<<<DLAT, 256>>>(dec_b_rw, rwth_b, rwtl_b, DLAT);
    wtsplit_kernel<<<DLAT, 256>>>(dec_b_rw + DLAT * DLAT, rwth_b + DLAT * DLAT,
                                  rwtl_b + DLAT * DLAT, DLAT);
    split1_kernel<<<(NCODE * DLAT / 4 + 255) / 256, 256>>>(codebook, eh, el,
                                                           NCODE * DLAT / 4);

    // encoders (exact scalar fp32 chains — argmin-critical, proven)
    gemm_kernel<true, false, false><<<dim3(2, BATCH / 64, 2), 256>>>(
        GArgs{x_a, enc_a_w, enc_a_b, ze_a0, nullptr, DINA},
        GArgs{x_b, enc_b_w, enc_b_b, ze_b0, nullptr, DINB});
    gemm_kernel<true, true, false><<<dim3(2, BATCH / 64, 2), 256>>>(
        GArgs{ze_a0, enc_a_rw, enc_a_rb, ze_a1, nullptr, DLAT},
        GArgs{ze_b0, enc_b_rw, enc_b_rb, ze_b1, nullptr, DLAT});
    // last res layer: fused bf16-hi z split for VQ phase 1
    gemm_kernel<true, true, true><<<dim3(2, BATCH / 64, 2), 256>>>(
        GArgs{ze_a1, enc_a_rw + DLAT * DLAT, enc_a_rb + DLAT, ze_a0, zh_a, DLAT},
        GArgs{ze_b1, enc_b_rw + DLAT * DLAT, enc_b_rb + DLAT, ze_b0, zh_b, DLAT});

    zz_kernel<<<dim3(BATCH / 8, 2), 256>>>(ze_a0, ze_b0, zz_a, zz_b);

    // VQ: single-term approx scores, then exact-chain resolve
    vq_mma_kernel<<<dim3(NCODE / 128, BATCH / 128, 2), 256>>>();
    vq_select_kernel<<<dim3(BATCH, 2), 256>>>(ze_a0, ze_b0, codebook);

    vq_finalize_kernel<<<dim3(BATCH / 8, 2), 256>>>(
        ze_a0, ze_b0, codebook,
        out + OFF_ZA, out + OFF_ZB, out + OFF_LA, out + OFF_LB);

    const float* Zq = out;

    // decoder res blocks (3-term, a+b merged)
    mma_res_kernel<true><<<dim3(2, 2 * BATCH / 128, 2), 256>>>(
        RArgs{Zq, zqh, zql, rwth_a, rwtl_a, dec_a_rb, h1a, s1h_a, s1l_a},
        RArgs{Zq, zqh, zql, rwth_b, rwtl_b, dec_b_rb, h1b, s1h_b, s1l_b});
    mma_res_kernel<false><<<dim3(2, 2 * BATCH / 128, 2), 256>>>(
        RArgs{h1a, s1h_a, s1l_a, rwth_a + DLAT * DLAT, rwtl_a + DLAT * DLAT,
              dec_a_rb + DLAT, nullptr, s0h_a, s0l_a},
        RArgs{h1b, s1h_b, s1l_b, rwth_b + DLAT * DLAT, rwtl_b + DLAT * DLAT,
              dec_b_rb + DLAT, nullptr, s0h_b, s0l_b});

    // decoder finals (a+b merged; b grid early-exits above nx=16)
    mma_final_kernel<<<dim3(DINA / 128, 2 * BATCH / 128, 2), 256>>>(
        FArgs{s0h_a, s0l_a, wth_a, wtl_a, dec_a_b,
              out + OFF_RA, out + OFF_XA, BATCH, DINA, DINA / 128},
        FArgs{s0h_b, s0l_b, wth_b, wtl_b, dec_b_b,
              out + OFF_XB, out + OFF_RB, BATCH, DINB, DINB / 128});
}